// round 4
// baseline (speedup 1.0000x reference)
#include <cuda_runtime.h>
#include <math.h>

// Problem constants
#define SB 2048          // sequence
#define EB 1024          // embed = head dim
#define NB 4             // batch
#define F3 3072          // 3*E

// ---------------- scratch (device globals: no allocation allowed) ----------
__device__ float g_qkv[NB * SB * F3];            // qkv output (q,k masked in place)
__device__ float g_norm[NB * (SB/2) * (EB/2)];   // 2x2 tile norms (reused q then k)
__device__ float g_rnorm[NB * SB];               // WO row norms
__device__ float g_thr[12];                      // [0..3]=q, [4..7]=k, [8..11]=WO
__device__ float g_wmask[NB * SB];               // WO row mask
__device__ float g_M1[NB * EB * EB];
__device__ float g_M2[NB * EB * EB];
__device__ float g_M3[NB * EB * EB];
__device__ float g_T1[NB * EB * EB];
__device__ float g_T2[NB * EB * EB];

// ======================= compensated q/k GEMM ==============================
// C[M,Ncols] = A[M,K] * B[Ncols,K]^T + bias[n], Neumaier-compensated fp32
// accumulation (near correctly-rounded). 64x64 block, 256 thr, TM=TN=4, kt=16.
__global__ __launch_bounds__(256) void gemm_nt_bias_comp(
    const float* __restrict__ A, const float* __restrict__ B,
    const float* __restrict__ bias, float* __restrict__ C,
    int M, int Ncols, int K, int ldc)
{
    __shared__ float As[16][64];
    __shared__ float Bs[16][64];
    const int tid = threadIdx.x;
    const int tx = tid & 15, ty = tid >> 4;
    const int m0 = blockIdx.y * 64, n0 = blockIdx.x * 64;
    const int lrow = tid >> 2, lk = (tid & 3) * 4;
    const float* Ap = A + (size_t)(m0 + lrow) * K + lk;
    const float* Bp = B + (size_t)(n0 + lrow) * K + lk;

    float s[4][4] = {{0.0f}};
    float c[4][4] = {{0.0f}};
    for (int k0 = 0; k0 < K; k0 += 16) {
        float4 av = *(const float4*)(Ap + k0);
        float4 bv = *(const float4*)(Bp + k0);
        As[lk+0][lrow] = av.x; As[lk+1][lrow] = av.y;
        As[lk+2][lrow] = av.z; As[lk+3][lrow] = av.w;
        Bs[lk+0][lrow] = bv.x; Bs[lk+1][lrow] = bv.y;
        Bs[lk+2][lrow] = bv.z; Bs[lk+3][lrow] = bv.w;
        __syncthreads();
        #pragma unroll
        for (int kk = 0; kk < 16; kk++) {
            float a[4], b[4];
            *(float4*)a = *(const float4*)&As[kk][ty*4];
            *(float4*)b = *(const float4*)&Bs[kk][tx*4];
            #pragma unroll
            for (int i = 0; i < 4; i++)
                #pragma unroll
                for (int j = 0; j < 4; j++) {
                    float p = __fmul_rn(a[i], b[j]);
                    float e = __fmaf_rn(a[i], b[j], -p);     // TwoProd error
                    float t = __fadd_rn(s[i][j], p);
                    float z = (fabsf(s[i][j]) >= fabsf(p))
                              ? __fadd_rn(__fadd_rn(s[i][j], -t), p)
                              : __fadd_rn(__fadd_rn(p, -t), s[i][j]);
                    c[i][j] = __fadd_rn(c[i][j], __fadd_rn(z, e));
                    s[i][j] = t;
                }
        }
        __syncthreads();
    }
    #pragma unroll
    for (int i = 0; i < 4; i++) {
        int m = m0 + ty*4 + i;
        #pragma unroll
        for (int j = 0; j < 4; j++) {
            int n = n0 + tx*4 + j;
            float v = __fadd_rn(s[i][j], c[i][j]);
            C[(size_t)m * ldc + n] = __fadd_rn(v, bias[n]);
        }
    }
}

// ======================= plain GEMM kernels (128x128x8, TM=TN=8) ===========

// C[M,*] (ldc) = A[M,K] * B[Ncols,K]^T + bias[n]
__global__ __launch_bounds__(256) void gemm_nt_bias(
    const float* __restrict__ A, const float* __restrict__ B,
    const float* __restrict__ bias, float* __restrict__ C,
    int M, int Ncols, int K, int ldc)
{
    __shared__ float As[8][128];
    __shared__ float Bs[8][128];
    const int tid = threadIdx.x;
    const int tx = tid & 15, ty = tid >> 4;
    const int m0 = blockIdx.y * 128, n0 = blockIdx.x * 128;
    const int lrow = tid >> 1, lk = (tid & 1) * 4;
    const float* Ap = A + (size_t)(m0 + lrow) * K + lk;
    const float* Bp = B + (size_t)(n0 + lrow) * K + lk;

    float acc[8][8] = {{0.0f}};
    for (int k0 = 0; k0 < K; k0 += 8) {
        float4 av = *(const float4*)(Ap + k0);
        float4 bv = *(const float4*)(Bp + k0);
        As[lk+0][lrow] = av.x; As[lk+1][lrow] = av.y;
        As[lk+2][lrow] = av.z; As[lk+3][lrow] = av.w;
        Bs[lk+0][lrow] = bv.x; Bs[lk+1][lrow] = bv.y;
        Bs[lk+2][lrow] = bv.z; Bs[lk+3][lrow] = bv.w;
        __syncthreads();
        #pragma unroll
        for (int kk = 0; kk < 8; kk++) {
            float a[8], b[8];
            *(float4*)(a)   = *(const float4*)&As[kk][ty*8];
            *(float4*)(a+4) = *(const float4*)&As[kk][ty*8+4];
            *(float4*)(b)   = *(const float4*)&Bs[kk][tx*8];
            *(float4*)(b+4) = *(const float4*)&Bs[kk][tx*8+4];
            #pragma unroll
            for (int i = 0; i < 8; i++)
                #pragma unroll
                for (int j = 0; j < 8; j++)
                    acc[i][j] = fmaf(a[i], b[j], acc[i][j]);
        }
        __syncthreads();
    }
    #pragma unroll
    for (int i = 0; i < 8; i++) {
        int m = m0 + ty*8 + i;
        #pragma unroll
        for (int j = 0; j < 8; j++) {
            int n = n0 + tx*8 + j;
            C[(size_t)m * ldc + n] = acc[i][j] + bias[n];
        }
    }
}

// C[M,N] = alpha * sum_k (kscale?[k]) * A[k,m] * B[k,n]
__global__ __launch_bounds__(256) void gemm_tn(
    const float* __restrict__ A, const float* __restrict__ B,
    const float* __restrict__ kscale, float* __restrict__ C,
    int M, int N, int K, int lda, int ldb, int ldc,
    long long aB, long long bB, long long cB, int ksB, float alpha)
{
    __shared__ float As[8][128];
    __shared__ float Bs[8][128];
    const int tid = threadIdx.x;
    const int tx = tid & 15, ty = tid >> 4;
    const int m0 = blockIdx.y * 128, n0 = blockIdx.x * 128;
    const int bz = blockIdx.z;
    const float* Ab = A + (size_t)bz * aB;
    const float* Bb = B + (size_t)bz * bB;
    float* Cb = C + (size_t)bz * cB;
    const float* ks = kscale ? kscale + (size_t)bz * ksB : nullptr;
    const int lk = tid >> 5;         // 0..7
    const int lm = (tid & 31) * 4;   // 0..124

    float acc[8][8] = {{0.0f}};
    for (int k0 = 0; k0 < K; k0 += 8) {
        float4 av = *(const float4*)(Ab + (size_t)(k0 + lk) * lda + m0 + lm);
        if (ks) {
            float sc = ks[k0 + lk];
            av.x *= sc; av.y *= sc; av.z *= sc; av.w *= sc;
        }
        float4 bv = *(const float4*)(Bb + (size_t)(k0 + lk) * ldb + n0 + lm);
        *(float4*)&As[lk][lm] = av;
        *(float4*)&Bs[lk][lm] = bv;
        __syncthreads();
        #pragma unroll
        for (int kk = 0; kk < 8; kk++) {
            float a[8], b[8];
            *(float4*)(a)   = *(const float4*)&As[kk][ty*8];
            *(float4*)(a+4) = *(const float4*)&As[kk][ty*8+4];
            *(float4*)(b)   = *(const float4*)&Bs[kk][tx*8];
            *(float4*)(b+4) = *(const float4*)&Bs[kk][tx*8+4];
            #pragma unroll
            for (int i = 0; i < 8; i++)
                #pragma unroll
                for (int j = 0; j < 8; j++)
                    acc[i][j] = fmaf(a[i], b[j], acc[i][j]);
        }
        __syncthreads();
    }
    #pragma unroll
    for (int i = 0; i < 8; i++) {
        int m = m0 + ty*8 + i;
        #pragma unroll
        for (int j = 0; j < 8; j++) {
            int n = n0 + tx*8 + j;
            Cb[(size_t)m * ldc + n] = alpha * acc[i][j];
        }
    }
}

// C[M,N] = alpha * A[M,K] * B[K,N]   (both row-major), batched over z
__global__ __launch_bounds__(256) void gemm_nn(
    const float* __restrict__ A, const float* __restrict__ B,
    float* __restrict__ C,
    int M, int N, int K, int lda, int ldb, int ldc,
    long long aB, long long bB, long long cB, float alpha)
{
    __shared__ float As[8][128];
    __shared__ float Bs[8][128];
    const int tid = threadIdx.x;
    const int tx = tid & 15, ty = tid >> 4;
    const int m0 = blockIdx.y * 128, n0 = blockIdx.x * 128;
    const int bz = blockIdx.z;
    const float* Ab = A + (size_t)bz * aB;
    const float* Bb = B + (size_t)bz * bB;
    float* Cb = C + (size_t)bz * cB;
    const int lrowA = tid >> 1, lkA = (tid & 1) * 4;
    const int lkB = tid >> 5, lnB = (tid & 31) * 4;

    float acc[8][8] = {{0.0f}};
    for (int k0 = 0; k0 < K; k0 += 8) {
        float4 av = *(const float4*)(Ab + (size_t)(m0 + lrowA) * lda + k0 + lkA);
        float4 bv = *(const float4*)(Bb + (size_t)(k0 + lkB) * ldb + n0 + lnB);
        As[lkA+0][lrowA] = av.x; As[lkA+1][lrowA] = av.y;
        As[lkA+2][lrowA] = av.z; As[lkA+3][lrowA] = av.w;
        *(float4*)&Bs[lkB][lnB] = bv;
        __syncthreads();
        #pragma unroll
        for (int kk = 0; kk < 8; kk++) {
            float a[8], b[8];
            *(float4*)(a)   = *(const float4*)&As[kk][ty*8];
            *(float4*)(a+4) = *(const float4*)&As[kk][ty*8+4];
            *(float4*)(b)   = *(const float4*)&Bs[kk][tx*8];
            *(float4*)(b+4) = *(const float4*)&Bs[kk][tx*8+4];
            #pragma unroll
            for (int i = 0; i < 8; i++)
                #pragma unroll
                for (int j = 0; j < 8; j++)
                    acc[i][j] = fmaf(a[i], b[j], acc[i][j]);
        }
        __syncthreads();
    }
    #pragma unroll
    for (int i = 0; i < 8; i++) {
        int m = m0 + ty*8 + i;
        #pragma unroll
        for (int j = 0; j < 8; j++) {
            int n = n0 + tx*8 + j;
            Cb[(size_t)m * ldc + n] = alpha * acc[i][j];
        }
    }
}

// ======================= pruning kernels ===================================

// 2x2 tile norms: squares individually rounded, linear reduce, IEEE sqrt.
__global__ void tile_norms_k(int off)
{
    int idx = blockIdx.x * 256 + threadIdx.x;     // 2097152
    int b  = idx >> 19;
    int r  = idx & 524287;
    int s2 = r >> 9, d2 = r & 511;
    size_t base = ((size_t)(b * SB + 2 * s2)) * F3 + off + 2 * d2;
    float2 a = *(const float2*)&g_qkv[base];
    float2 c = *(const float2*)&g_qkv[base + F3];
    float s00 = __fmul_rn(a.x, a.x);
    float s01 = __fmul_rn(a.y, a.y);
    float s10 = __fmul_rn(c.x, c.x);
    float s11 = __fmul_rn(c.y, c.y);
    float t = __fadd_rn(__fadd_rn(__fadd_rn(s00, s01), s10), s11);
    g_norm[idx] = sqrtf(t);
}

__global__ void mask_tiles_k(int off, int thrBase)
{
    int idx = blockIdx.x * 256 + threadIdx.x;
    int b  = idx >> 19;
    int r  = idx & 524287;
    int s2 = r >> 9, d2 = r & 511;
    float thr = g_thr[thrBase + b];
    if (g_norm[idx] < thr) {
        size_t base = ((size_t)(b * SB + 2 * s2)) * F3 + off + 2 * d2;
        float2 z = make_float2(0.0f, 0.0f);
        *(float2*)&g_qkv[base]      = z;
        *(float2*)&g_qkv[base + F3] = z;
    }
}

// WO row norms with Neumaier compensation (near-exact sum of squares):
// kills reduction-order sensitivity at the WO median boundary.
__global__ void wo_rownorm_k(const float* __restrict__ WO)
{
    int warp = threadIdx.x >> 5, lane = threadIdx.x & 31;
    int row = blockIdx.x * 8 + warp;              // 8192 rows
    const float* p = WO + (size_t)row * EB;
    float s = 0.0f, c = 0.0f;
    for (int d = lane; d < EB; d += 32) {
        float v = p[d];
        float pr = __fmul_rn(v, v);
        float e  = __fmaf_rn(v, v, -pr);
        float t  = __fadd_rn(s, pr);
        float z  = (fabsf(s) >= fabsf(pr))
                   ? __fadd_rn(__fadd_rn(s, -t), pr)
                   : __fadd_rn(__fadd_rn(pr, -t), s);
        c = __fadd_rn(c, __fadd_rn(z, e));
        s = t;
    }
    // combine (s,c) pairs across lanes: sum s with compensation, plus all c
    float tot_s = s, tot_c = c;
    #pragma unroll
    for (int o = 16; o; o >>= 1) {
        float os = __shfl_xor_sync(0xffffffffu, tot_s, o);
        float oc = __shfl_xor_sync(0xffffffffu, tot_c, o);
        float t = __fadd_rn(tot_s, os);
        float z = (fabsf(tot_s) >= fabsf(os))
                  ? __fadd_rn(__fadd_rn(tot_s, -t), os)
                  : __fadd_rn(__fadd_rn(os, -t), tot_s);
        tot_c = __fadd_rn(__fadd_rn(tot_c, oc), z);
        tot_s = t;
    }
    if (lane == 0) g_rnorm[row] = sqrtf(__fadd_rn(tot_s, tot_c));
}

// exact median via radix select on float bits (data >= 0)
__global__ __launch_bounds__(1024) void select_median_k(
    const float* __restrict__ data, int N, int k1, int k2, float* __restrict__ out)
{
    __shared__ unsigned hist[256];
    __shared__ unsigned s_prefix, s_pmask;
    __shared__ int s_k;
    __shared__ float s_v[2];
    const float* d = data + (size_t)blockIdx.x * N;
    const int tid = threadIdx.x;

    for (int which = 0; which < 2; which++) {
        int k = which ? k2 : k1;
        unsigned prefix = 0, pmask = 0;
        for (int pass = 0; pass < 4; pass++) {
            int shift = 24 - 8 * pass;
            if (tid < 256) hist[tid] = 0;
            __syncthreads();
            for (int i = tid; i < N; i += 1024) {
                unsigned u = __float_as_uint(d[i]);
                if ((u & pmask) == prefix) atomicAdd(&hist[(u >> shift) & 255], 1u);
            }
            __syncthreads();
            if (tid == 0) {
                int cum = 0, bin = 0;
                for (; bin < 256; bin++) {
                    int cc = (int)hist[bin];
                    if (cum + cc > k) break;
                    cum += cc;
                }
                s_prefix = prefix | ((unsigned)bin << shift);
                s_pmask  = pmask  | (255u << shift);
                s_k = k - cum;
            }
            __syncthreads();
            prefix = s_prefix; pmask = s_pmask; k = s_k;
        }
        if (tid == 0) s_v[which] = __uint_as_float(prefix);
        __syncthreads();
    }
    if (tid == 0) out[blockIdx.x] = __fmul_rn(0.5f, __fadd_rn(s_v[0], s_v[1]));
}

__global__ void wmask_k()
{
    int idx = blockIdx.x * 256 + threadIdx.x;     // 8192
    int b = idx >> 11;
    g_wmask[idx] = (g_rnorm[idx] >= g_thr[8 + b]) ? 1.0f : 0.0f;
}

// ======================= launch ============================================
extern "C" void kernel_launch(void* const* d_in, const int* in_sizes, int n_in,
                              void* d_out, int out_size)
{
    const float* x    = (const float*)d_in[0];  // [B,S,E]
    const float* Wqkv = (const float*)d_in[1];  // [3E,E]
    const float* bqkv = (const float*)d_in[2];  // [3E]
    const float* WO   = (const float*)d_in[3];  // [B,1,S,hd]
    float* out = (float*)d_out;                 // [B,S,E]

    float *qkv, *norm, *rnorm, *thr, *M1, *M2, *M3, *T1, *T2, *wmask;
    cudaGetSymbolAddress((void**)&qkv,   g_qkv);
    cudaGetSymbolAddress((void**)&norm,  g_norm);
    cudaGetSymbolAddress((void**)&rnorm, g_rnorm);
    cudaGetSymbolAddress((void**)&thr,   g_thr);
    cudaGetSymbolAddress((void**)&wmask, g_wmask);
    cudaGetSymbolAddress((void**)&M1,    g_M1);
    cudaGetSymbolAddress((void**)&M2,    g_M2);
    cudaGetSymbolAddress((void**)&M3,    g_M3);
    cudaGetSymbolAddress((void**)&T1,    g_T1);
    cudaGetSymbolAddress((void**)&T2,    g_T2);

    // 1a) q,k = x @ Wqkv[0:2048]^T  (compensated, near correctly rounded)
    {
        dim3 grid(2048 / 64, (NB * SB) / 64);       // (32,128)
        gemm_nt_bias_comp<<<grid, 256>>>(x, Wqkv, bqkv, qkv,
                                         NB * SB, 2048, EB, F3);
    }
    // 1b) v = x @ Wqkv[2048:3072]^T  (plain)
    {
        dim3 grid(1024 / 128, (NB * SB) / 128);     // (8,64)
        gemm_nt_bias<<<grid, 256>>>(x, Wqkv + (size_t)2048 * EB, bqkv + 2048,
                                    qkv + 2048, NB * SB, 1024, EB, F3);
    }

    // 2) tile pruning of q and k (in place in qkv)
    tile_norms_k<<<8192, 256>>>(0);
    select_median_k<<<NB, 1024>>>(norm, 524288, 262143, 262144, thr + 0);
    mask_tiles_k<<<8192, 256>>>(0, 0);

    tile_norms_k<<<8192, 256>>>(EB);
    select_median_k<<<NB, 1024>>>(norm, 524288, 262143, 262144, thr + 4);
    mask_tiles_k<<<8192, 256>>>(EB, 4);

    // 3) row pruning of WO -> mask
    wo_rownorm_k<<<1024, 256>>>(WO);
    select_median_k<<<NB, 1024>>>(rnorm, SB, 1023, 1024, thr + 8);
    wmask_k<<<32, 256>>>();

    // 4) chain: out = x * [ (1/32 Qp^T Kp) * (x^T v) * (WOp^T x) ]
    const long long sqkv = (long long)SB * F3;
    const long long sxe  = (long long)SB * EB;
    const long long see  = (long long)EB * EB;
    dim3 gE(EB / 128, EB / 128, NB);   // (8,8,4)

    gemm_tn<<<gE, 256>>>(qkv,      qkv + EB,   nullptr, M1, EB, EB, SB,
                         F3, F3, EB, sqkv, sqkv, see, 0, 1.0f / 32.0f);
    gemm_tn<<<gE, 256>>>(x,        qkv + 2*EB, nullptr, M2, EB, EB, SB,
                         EB, F3, EB, sxe, sqkv, see, 0, 1.0f);
    gemm_tn<<<gE, 256>>>(WO,       x,          wmask,   M3, EB, EB, SB,
                         EB, EB, EB, sxe, sxe, see, SB, 1.0f);
    gemm_nn<<<gE, 256>>>(M1, M2, T1, EB, EB, EB, EB, EB, EB, see, see, see, 1.0f);
    gemm_nn<<<gE, 256>>>(T1, M3, T2, EB, EB, EB, EB, EB, EB, see, see, see, 1.0f);
    dim3 gO(EB / 128, SB / 128, NB);   // (8,16,4)
    gemm_nn<<<gO, 256>>>(x, T2, out, SB, EB, EB, EB, EB, EB, sxe, see, sxe, 1.0f);
}

// round 5
// speedup vs baseline: 1.5093x; 1.5093x over previous
#include <cuda_runtime.h>
#include <math.h>

// Problem constants
#define SB 2048          // sequence
#define EB 1024          // embed = head dim
#define NB 4             // batch
#define F3 3072          // 3*E
#define NTILES 524288    // (SB/2)*(EB/2) per batch
#define CAP 16384        // candidate capacity per group
#define HBINS 8192
#define DELTA 2.5e-3f

// ---------------- scratch (device globals: no allocation allowed) ----------
__device__ float g_qkv[NB * SB * F3];
__device__ float g_normq[NB * NTILES];
__device__ float g_normk[NB * NTILES];
__device__ float g_rnorm[NB * SB];
__device__ float g_thr[12];              // [0..3]=q, [4..7]=k, [8..11]=WO
__device__ float g_thra[8];              // approx thresholds (q:0..3, k:4..7)
__device__ float g_wmask[NB * SB];
__device__ unsigned g_hist[8 * HBINS];
__device__ unsigned g_ccnt[8];
__device__ unsigned g_below[8];
__device__ int   g_cidx[8 * CAP];
__device__ float g_cval[8 * CAP * 4];
__device__ float g_cnorm[8 * CAP];
__device__ float g_M1[NB * EB * EB];
__device__ float g_M2[NB * EB * EB];
__device__ float g_M3[NB * EB * EB];
__device__ float g_T1[NB * EB * EB];
__device__ float g_T2[NB * EB * EB];

// ======================= plain GEMMs (128x128x16, TM=TN=8) =================

// C[M,*](ldc) = A[M,K] * B[Ncols,K]^T + bias[n]
__global__ __launch_bounds__(256) void gemm_nt_bias16(
    const float* __restrict__ A, const float* __restrict__ B,
    const float* __restrict__ bias, float* __restrict__ C,
    int M, int Ncols, int K, int ldc)
{
    __shared__ float As[16][128];
    __shared__ float Bs[16][128];
    const int tid = threadIdx.x;
    const int tx = tid & 15, ty = tid >> 4;
    const int m0 = blockIdx.y * 128, n0 = blockIdx.x * 128;
    const int lrow = tid >> 1, lk = (tid & 1) * 8;
    const float* Ap = A + (size_t)(m0 + lrow) * K + lk;
    const float* Bp = B + (size_t)(n0 + lrow) * K + lk;

    float acc[8][8] = {{0.0f}};
    for (int k0 = 0; k0 < K; k0 += 16) {
        float4 a0 = *(const float4*)(Ap + k0);
        float4 a1 = *(const float4*)(Ap + k0 + 4);
        float4 b0 = *(const float4*)(Bp + k0);
        float4 b1 = *(const float4*)(Bp + k0 + 4);
        As[lk+0][lrow] = a0.x; As[lk+1][lrow] = a0.y;
        As[lk+2][lrow] = a0.z; As[lk+3][lrow] = a0.w;
        As[lk+4][lrow] = a1.x; As[lk+5][lrow] = a1.y;
        As[lk+6][lrow] = a1.z; As[lk+7][lrow] = a1.w;
        Bs[lk+0][lrow] = b0.x; Bs[lk+1][lrow] = b0.y;
        Bs[lk+2][lrow] = b0.z; Bs[lk+3][lrow] = b0.w;
        Bs[lk+4][lrow] = b1.x; Bs[lk+5][lrow] = b1.y;
        Bs[lk+6][lrow] = b1.z; Bs[lk+7][lrow] = b1.w;
        __syncthreads();
        #pragma unroll
        for (int kk = 0; kk < 16; kk++) {
            float a[8], b[8];
            *(float4*)(a)   = *(const float4*)&As[kk][ty*8];
            *(float4*)(a+4) = *(const float4*)&As[kk][ty*8+4];
            *(float4*)(b)   = *(const float4*)&Bs[kk][tx*8];
            *(float4*)(b+4) = *(const float4*)&Bs[kk][tx*8+4];
            #pragma unroll
            for (int i = 0; i < 8; i++)
                #pragma unroll
                for (int j = 0; j < 8; j++)
                    acc[i][j] = fmaf(a[i], b[j], acc[i][j]);
        }
        __syncthreads();
    }
    #pragma unroll
    for (int i = 0; i < 8; i++) {
        int m = m0 + ty*8 + i;
        #pragma unroll
        for (int j = 0; j < 8; j++) {
            int n = n0 + tx*8 + j;
            C[(size_t)m * ldc + n] = acc[i][j] + bias[n];
        }
    }
}

// C[M,N] = alpha * sum_k (kscale?[k]) * A[k,m] * B[k,n]   (kt=16)
__global__ __launch_bounds__(256) void gemm_tn16(
    const float* __restrict__ A, const float* __restrict__ B,
    const float* __restrict__ kscale, float* __restrict__ C,
    int M, int N, int K, int lda, int ldb, int ldc,
    long long aB, long long bB, long long cB, int ksB, float alpha)
{
    __shared__ float As[16][128];
    __shared__ float Bs[16][128];
    const int tid = threadIdx.x;
    const int tx = tid & 15, ty = tid >> 4;
    const int m0 = blockIdx.y * 128, n0 = blockIdx.x * 128;
    const int bz = blockIdx.z;
    const float* Ab = A + (size_t)bz * aB;
    const float* Bb = B + (size_t)bz * bB;
    float* Cb = C + (size_t)bz * cB;
    const float* ks = kscale ? kscale + (size_t)bz * ksB : nullptr;
    const int lk = tid >> 4;          // 0..15
    const int lm = (tid & 15) * 8;    // 0..120

    float acc[8][8] = {{0.0f}};
    for (int k0 = 0; k0 < K; k0 += 16) {
        float4 a0 = *(const float4*)(Ab + (size_t)(k0 + lk) * lda + m0 + lm);
        float4 a1 = *(const float4*)(Ab + (size_t)(k0 + lk) * lda + m0 + lm + 4);
        if (ks) {
            float sc = ks[k0 + lk];
            a0.x *= sc; a0.y *= sc; a0.z *= sc; a0.w *= sc;
            a1.x *= sc; a1.y *= sc; a1.z *= sc; a1.w *= sc;
        }
        float4 b0 = *(const float4*)(Bb + (size_t)(k0 + lk) * ldb + n0 + lm);
        float4 b1 = *(const float4*)(Bb + (size_t)(k0 + lk) * ldb + n0 + lm + 4);
        *(float4*)&As[lk][lm]   = a0;
        *(float4*)&As[lk][lm+4] = a1;
        *(float4*)&Bs[lk][lm]   = b0;
        *(float4*)&Bs[lk][lm+4] = b1;
        __syncthreads();
        #pragma unroll
        for (int kk = 0; kk < 16; kk++) {
            float a[8], b[8];
            *(float4*)(a)   = *(const float4*)&As[kk][ty*8];
            *(float4*)(a+4) = *(const float4*)&As[kk][ty*8+4];
            *(float4*)(b)   = *(const float4*)&Bs[kk][tx*8];
            *(float4*)(b+4) = *(const float4*)&Bs[kk][tx*8+4];
            #pragma unroll
            for (int i = 0; i < 8; i++)
                #pragma unroll
                for (int j = 0; j < 8; j++)
                    acc[i][j] = fmaf(a[i], b[j], acc[i][j]);
        }
        __syncthreads();
    }
    #pragma unroll
    for (int i = 0; i < 8; i++) {
        int m = m0 + ty*8 + i;
        #pragma unroll
        for (int j = 0; j < 8; j++) {
            int n = n0 + tx*8 + j;
            Cb[(size_t)m * ldc + n] = alpha * acc[i][j];
        }
    }
}

// C[M,N] = alpha * A[M,K] * B[K,N]  (row-major), batched, kt=16
__global__ __launch_bounds__(256) void gemm_nn16(
    const float* __restrict__ A, const float* __restrict__ B,
    float* __restrict__ C,
    int M, int N, int K, int lda, int ldb, int ldc,
    long long aB, long long bB, long long cB, float alpha)
{
    __shared__ float As[16][128];
    __shared__ float Bs[16][128];
    const int tid = threadIdx.x;
    const int tx = tid & 15, ty = tid >> 4;
    const int m0 = blockIdx.y * 128, n0 = blockIdx.x * 128;
    const int bz = blockIdx.z;
    const float* Ab = A + (size_t)bz * aB;
    const float* Bb = B + (size_t)bz * bB;
    float* Cb = C + (size_t)bz * cB;
    const int lrowA = tid >> 1, lkA = (tid & 1) * 8;
    const int lkB = tid >> 4, lnB = (tid & 15) * 8;

    float acc[8][8] = {{0.0f}};
    for (int k0 = 0; k0 < K; k0 += 16) {
        float4 a0 = *(const float4*)(Ab + (size_t)(m0 + lrowA) * lda + k0 + lkA);
        float4 a1 = *(const float4*)(Ab + (size_t)(m0 + lrowA) * lda + k0 + lkA + 4);
        float4 b0 = *(const float4*)(Bb + (size_t)(k0 + lkB) * ldb + n0 + lnB);
        float4 b1 = *(const float4*)(Bb + (size_t)(k0 + lkB) * ldb + n0 + lnB + 4);
        As[lkA+0][lrowA] = a0.x; As[lkA+1][lrowA] = a0.y;
        As[lkA+2][lrowA] = a0.z; As[lkA+3][lrowA] = a0.w;
        As[lkA+4][lrowA] = a1.x; As[lkA+5][lrowA] = a1.y;
        As[lkA+6][lrowA] = a1.z; As[lkA+7][lrowA] = a1.w;
        *(float4*)&Bs[lkB][lnB]   = b0;
        *(float4*)&Bs[lkB][lnB+4] = b1;
        __syncthreads();
        #pragma unroll
        for (int kk = 0; kk < 16; kk++) {
            float a[8], b[8];
            *(float4*)(a)   = *(const float4*)&As[kk][ty*8];
            *(float4*)(a+4) = *(const float4*)&As[kk][ty*8+4];
            *(float4*)(b)   = *(const float4*)&Bs[kk][tx*8];
            *(float4*)(b+4) = *(const float4*)&Bs[kk][tx*8+4];
            #pragma unroll
            for (int i = 0; i < 8; i++)
                #pragma unroll
                for (int j = 0; j < 8; j++)
                    acc[i][j] = fmaf(a[i], b[j], acc[i][j]);
        }
        __syncthreads();
    }
    #pragma unroll
    for (int i = 0; i < 8; i++) {
        int m = m0 + ty*8 + i;
        #pragma unroll
        for (int j = 0; j < 8; j++) {
            int n = n0 + tx*8 + j;
            Cb[(size_t)m * ldc + n] = alpha * acc[i][j];
        }
    }
}

// ======================= pruning pipeline ==================================

__global__ void zero_k()
{
    int i = blockIdx.x * 256 + threadIdx.x;
    if (i < 8 * HBINS) g_hist[i] = 0;
    if (i < 8) { g_ccnt[i] = 0; g_below[i] = 0; }
}

// plain tile norms for q and k + histogram (bin width 1/1024 over [0,8))
__global__ void norms_hist_k()
{
    int idx = blockIdx.x * 256 + threadIdx.x;     // 2097152
    int b  = idx >> 19;
    int r  = idx & (NTILES - 1);
    int s2 = r >> 9, d2 = r & 511;
    size_t base = ((size_t)(b * SB + 2 * s2)) * F3 + 2 * d2;
    #pragma unroll
    for (int qk = 0; qk < 2; qk++) {
        size_t p = base + qk * EB;
        float2 a = *(const float2*)&g_qkv[p];
        float2 c = *(const float2*)&g_qkv[p + F3];
        float s00 = __fmul_rn(a.x, a.x);
        float s01 = __fmul_rn(a.y, a.y);
        float s10 = __fmul_rn(c.x, c.x);
        float s11 = __fmul_rn(c.y, c.y);
        float nm = sqrtf(__fadd_rn(__fadd_rn(__fadd_rn(s00, s01), s10), s11));
        if (qk == 0) g_normq[idx] = nm; else g_normk[idx] = nm;
        int bin = (int)(nm * 1024.0f);
        if (bin < 0) bin = 0;
        if (bin > HBINS - 1) bin = HBINS - 1;
        atomicAdd(&g_hist[(qk * 4 + b) * HBINS + bin], 1u);
    }
}

// approx median per group from histogram (bin center)
__global__ void approx_median_k()
{
    int g = blockIdx.x;       // 0..7
    if (threadIdx.x != 0) return;
    const unsigned* h = &g_hist[g * HBINS];
    unsigned k = 262143;
    unsigned cum = 0; int bin = 0;
    for (; bin < HBINS; bin++) {
        unsigned c = h[bin];
        if (cum + c > k) break;
        cum += c;
    }
    g_thra[g] = ((float)bin + 0.5f) * (1.0f / 1024.0f);
}

// gather candidates (|norm - thra| <= DELTA) and count definite-below
__global__ void candidates_k()
{
    int idx = blockIdx.x * 256 + threadIdx.x;
    int b = idx >> 19;
    int r = idx & (NTILES - 1);
    #pragma unroll
    for (int qk = 0; qk < 2; qk++) {
        float nm = qk ? g_normk[idx] : g_normq[idx];
        int g = qk * 4 + b;
        float d = nm - g_thra[g];
        if (fabsf(d) <= DELTA) {
            unsigned pos = atomicAdd(&g_ccnt[g], 1u);
            if (pos < CAP) g_cidx[g * CAP + pos] = r;
        } else if (d < 0.0f) {
            atomicAdd(&g_below[g], 1u);
        }
    }
}

// bit-identical replica of the R4 compensated dot: sequential k, TwoProd +
// Neumaier, then v=s+c, then +bias.
__device__ __forceinline__ float comp_dot(
    const float* __restrict__ a, const float* __restrict__ b, float bias)
{
    float s = 0.0f, c = 0.0f;
    for (int k = 0; k < EB; k++) {
        float av = a[k], bv = b[k];
        float p = __fmul_rn(av, bv);
        float e = __fmaf_rn(av, bv, -p);
        float t = __fadd_rn(s, p);
        float z = (fabsf(s) >= fabsf(p))
                  ? __fadd_rn(__fadd_rn(s, -t), p)
                  : __fadd_rn(__fadd_rn(p, -t), s);
        c = __fadd_rn(c, __fadd_rn(z, e));
        s = t;
    }
    float v = __fadd_rn(s, c);
    return __fadd_rn(v, bias);
}

// one thread per (group, candidate, element 0..3)
__global__ void exact_dots_k(const float* __restrict__ x,
                             const float* __restrict__ Wqkv,
                             const float* __restrict__ bqkv)
{
    int flat = blockIdx.x * 256 + threadIdx.x;    // 8*CAP*4
    int e    = flat & 3;
    int cand = (flat >> 2) & (CAP - 1);
    int g    = flat >> 16;                        // CAP*4 = 65536 per group
    if (g >= 8) return;
    unsigned cnt = g_ccnt[g]; if (cnt > CAP) cnt = CAP;
    if ((unsigned)cand >= cnt) return;
    int r  = g_cidx[g * CAP + cand];
    int qk = g >> 2, b = g & 3;
    int s2 = r >> 9, d2 = r & 511;
    int srow = 2 * s2 + (e >> 1);
    int dcol = 2 * d2 + (e & 1) + qk * EB;
    float v = comp_dot(x + ((size_t)(b * SB + srow)) * EB,
                       Wqkv + (size_t)dcol * EB, bqkv[dcol]);
    g_cval[(size_t)(g * CAP + cand) * 4 + e] = v;
}

// exact candidate norms (same formula as norms), write back into norm arrays
__global__ void exact_norm_k()
{
    int flat = blockIdx.x * 256 + threadIdx.x;    // 8*CAP
    int cand = flat & (CAP - 1);
    int g    = flat >> 14;
    if (g >= 8) return;
    unsigned cnt = g_ccnt[g]; if (cnt > CAP) cnt = CAP;
    if ((unsigned)cand >= cnt) return;
    const float* v = &g_cval[(size_t)(g * CAP + cand) * 4];
    float s00 = __fmul_rn(v[0], v[0]);
    float s01 = __fmul_rn(v[1], v[1]);
    float s10 = __fmul_rn(v[2], v[2]);
    float s11 = __fmul_rn(v[3], v[3]);
    float nm = sqrtf(__fadd_rn(__fadd_rn(__fadd_rn(s00, s01), s10), s11));
    g_cnorm[g * CAP + cand] = nm;
    int r = g_cidx[g * CAP + cand];
    int b = g & 3;
    if ((g >> 2) == 0) g_normq[b * NTILES + r] = nm;
    else               g_normk[b * NTILES + r] = nm;
}

// rank-select the two middle order statistics among candidates -> exact thr
__global__ __launch_bounds__(1024) void cand_select_k()
{
    __shared__ float s_v1, s_v2;
    int g = blockIdx.x;
    unsigned cnt = g_ccnt[g]; if (cnt > CAP) cnt = CAP;
    long long below = (long long)g_below[g];
    long long r1 = 262143LL - below;
    long long r2 = 262144LL - below;
    const float* cn = &g_cnorm[g * CAP];
    for (unsigned i = threadIdx.x; i < cnt; i += 1024) {
        float v = cn[i];
        long long less = 0, eq = 0;
        for (unsigned j = 0; j < cnt; j++) {
            float w = cn[j];
            less += (w < v);
            eq   += (w == v);
        }
        if (less <= r1 && r1 < less + eq) s_v1 = v;
        if (less <= r2 && r2 < less + eq) s_v2 = v;
    }
    __syncthreads();
    if (threadIdx.x == 0)
        g_thr[g] = __fmul_rn(0.5f, __fadd_rn(s_v1, s_v2));
}

// mask q and k tiles in place using exact thresholds
__global__ void mask_tiles2_k()
{
    int idx = blockIdx.x * 256 + threadIdx.x;
    int b = idx >> 19;
    int r = idx & (NTILES - 1);
    int s2 = r >> 9, d2 = r & 511;
    size_t base = ((size_t)(b * SB + 2 * s2)) * F3 + 2 * d2;
    float2 z = make_float2(0.0f, 0.0f);
    if (g_normq[idx] < g_thr[b]) {
        *(float2*)&g_qkv[base]      = z;
        *(float2*)&g_qkv[base + F3] = z;
    }
    if (g_normk[idx] < g_thr[4 + b]) {
        *(float2*)&g_qkv[base + EB]      = z;
        *(float2*)&g_qkv[base + EB + F3] = z;
    }
}

// ---- WO path (kept bit-identical to R4) ----
__global__ void wo_rownorm_k(const float* __restrict__ WO)
{
    int warp = threadIdx.x >> 5, lane = threadIdx.x & 31;
    int row = blockIdx.x * 8 + warp;
    const float* p = WO + (size_t)row * EB;
    float s = 0.0f, c = 0.0f;
    for (int d = lane; d < EB; d += 32) {
        float v = p[d];
        float pr = __fmul_rn(v, v);
        float e  = __fmaf_rn(v, v, -pr);
        float t  = __fadd_rn(s, pr);
        float z  = (fabsf(s) >= fabsf(pr))
                   ? __fadd_rn(__fadd_rn(s, -t), pr)
                   : __fadd_rn(__fadd_rn(pr, -t), s);
        c = __fadd_rn(c, __fadd_rn(z, e));
        s = t;
    }
    float tot_s = s, tot_c = c;
    #pragma unroll
    for (int o = 16; o; o >>= 1) {
        float os = __shfl_xor_sync(0xffffffffu, tot_s, o);
        float oc = __shfl_xor_sync(0xffffffffu, tot_c, o);
        float t = __fadd_rn(tot_s, os);
        float z = (fabsf(tot_s) >= fabsf(os))
                  ? __fadd_rn(__fadd_rn(tot_s, -t), os)
                  : __fadd_rn(__fadd_rn(os, -t), tot_s);
        tot_c = __fadd_rn(__fadd_rn(tot_c, oc), z);
        tot_s = t;
    }
    if (lane == 0) g_rnorm[row] = sqrtf(__fadd_rn(tot_s, tot_c));
}

__global__ __launch_bounds__(1024) void select_median_k(
    const float* __restrict__ data, int N, int k1, int k2, float* __restrict__ out)
{
    __shared__ unsigned hist[256];
    __shared__ unsigned s_prefix, s_pmask;
    __shared__ int s_k;
    __shared__ float s_v[2];
    const float* d = data + (size_t)blockIdx.x * N;
    const int tid = threadIdx.x;
    for (int which = 0; which < 2; which++) {
        int k = which ? k2 : k1;
        unsigned prefix = 0, pmask = 0;
        for (int pass = 0; pass < 4; pass++) {
            int shift = 24 - 8 * pass;
            if (tid < 256) hist[tid] = 0;
            __syncthreads();
            for (int i = tid; i < N; i += 1024) {
                unsigned u = __float_as_uint(d[i]);
                if ((u & pmask) == prefix) atomicAdd(&hist[(u >> shift) & 255], 1u);
            }
            __syncthreads();
            if (tid == 0) {
                int cum = 0, bin = 0;
                for (; bin < 256; bin++) {
                    int cc = (int)hist[bin];
                    if (cum + cc > k) break;
                    cum += cc;
                }
                s_prefix = prefix | ((unsigned)bin << shift);
                s_pmask  = pmask  | (255u << shift);
                s_k = k - cum;
            }
            __syncthreads();
            prefix = s_prefix; pmask = s_pmask; k = s_k;
        }
        if (tid == 0) s_v[which] = __uint_as_float(prefix);
        __syncthreads();
    }
    if (tid == 0) out[blockIdx.x] = __fmul_rn(0.5f, __fadd_rn(s_v[0], s_v[1]));
}

__global__ void wmask_k()
{
    int idx = blockIdx.x * 256 + threadIdx.x;
    int b = idx >> 11;
    g_wmask[idx] = (g_rnorm[idx] >= g_thr[8 + b]) ? 1.0f : 0.0f;
}

// ======================= launch ============================================
extern "C" void kernel_launch(void* const* d_in, const int* in_sizes, int n_in,
                              void* d_out, int out_size)
{
    const float* x    = (const float*)d_in[0];
    const float* Wqkv = (const float*)d_in[1];
    const float* bqkv = (const float*)d_in[2];
    const float* WO   = (const float*)d_in[3];
    float* out = (float*)d_out;

    float *qkv, *rnorm, *thr, *M1, *M2, *M3, *T1, *T2, *wmask;
    cudaGetSymbolAddress((void**)&qkv,   g_qkv);
    cudaGetSymbolAddress((void**)&rnorm, g_rnorm);
    cudaGetSymbolAddress((void**)&thr,   g_thr);
    cudaGetSymbolAddress((void**)&wmask, g_wmask);
    cudaGetSymbolAddress((void**)&M1,    g_M1);
    cudaGetSymbolAddress((void**)&M2,    g_M2);
    cudaGetSymbolAddress((void**)&M3,    g_M3);
    cudaGetSymbolAddress((void**)&T1,    g_T1);
    cudaGetSymbolAddress((void**)&T2,    g_T2);

    // 0) zero counters/hist
    zero_k<<<(8 * HBINS + 255) / 256, 256>>>();

    // 1) full qkv plain
    {
        dim3 grid(F3 / 128, (NB * SB) / 128);
        gemm_nt_bias16<<<grid, 256>>>(x, Wqkv, bqkv, qkv, NB * SB, F3, EB, F3);
    }

    // 2) tile pruning with lazy-exact boundary resolution
    norms_hist_k<<<8192, 256>>>();
    approx_median_k<<<8, 32>>>();
    candidates_k<<<8192, 256>>>();
    exact_dots_k<<<8 * CAP * 4 / 256, 256>>>(x, Wqkv, bqkv);
    exact_norm_k<<<8 * CAP / 256, 256>>>();
    cand_select_k<<<8, 1024>>>();
    mask_tiles2_k<<<8192, 256>>>();

    // 3) WO row pruning (bit-identical to R4)
    wo_rownorm_k<<<1024, 256>>>(WO);
    select_median_k<<<NB, 1024>>>(rnorm, SB, 1023, 1024, thr + 8);
    wmask_k<<<32, 256>>>();

    // 4) chain: out = x * [ (1/32 Qp^T Kp) * (x^T v) * (WOp^T x) ]
    const long long sqkv = (long long)SB * F3;
    const long long sxe  = (long long)SB * EB;
    const long long see  = (long long)EB * EB;
    dim3 gE(EB / 128, EB / 128, NB);

    gemm_tn16<<<gE, 256>>>(qkv,      qkv + EB,   nullptr, M1, EB, EB, SB,
                           F3, F3, EB, sqkv, sqkv, see, 0, 1.0f / 32.0f);
    gemm_tn16<<<gE, 256>>>(x,        qkv + 2*EB, nullptr, M2, EB, EB, SB,
                           EB, F3, EB, sxe, sqkv, see, 0, 1.0f);
    gemm_tn16<<<gE, 256>>>(WO,       x,          wmask,   M3, EB, EB, SB,
                           EB, EB, EB, sxe, sxe, see, SB, 1.0f);
    gemm_nn16<<<gE, 256>>>(M1, M2, T1, EB, EB, EB, EB, EB, EB, see, see, see, 1.0f);
    gemm_nn16<<<gE, 256>>>(T1, M3, T2, EB, EB, EB, EB, EB, EB, see, see, see, 1.0f);
    dim3 gO(EB / 128, SB / 128, NB);
    gemm_nn16<<<gO, 256>>>(x, T2, out, SB, EB, EB, EB, EB, EB, sxe, see, sxe, 1.0f);
}

// round 7
// speedup vs baseline: 2.1614x; 1.4320x over previous
#include <cuda_runtime.h>
#include <cuda_bf16.h>
#include <math.h>
#include <stdint.h>

// Problem constants
#define SB 2048
#define EB 1024
#define NB 4
#define F3 3072
#define NTILES 524288
#define CAP 16384
#define HBINS 8192
#define DELTA 2.5e-3f

// ---------------- scratch (device globals) ---------------------------------
__device__ float g_qkv[NB * SB * F3];
__device__ float g_normq[NB * NTILES];
__device__ float g_normk[NB * NTILES];
__device__ float g_rnorm[NB * SB];
__device__ float g_thr[12];
__device__ float g_thra[8];
__device__ float g_wmask[NB * SB];
__device__ unsigned g_hist[8 * HBINS];
__device__ unsigned g_ccnt[8];
__device__ unsigned g_below[8];
__device__ int   g_cidx[8 * CAP];
__device__ float g_cval[8 * CAP * 4];
__device__ float g_cnorm[8 * CAP];
__device__ float g_M1[NB * EB * EB];
__device__ float g_M2[NB * EB * EB];
__device__ float g_M3[NB * EB * EB];
__device__ float g_T1[NB * EB * EB];
__device__ float g_T2[NB * EB * EB];

// bf16 split operands (plain row-major, ld = K)
__device__ __align__(16) __nv_bfloat16 g_xs_h[8388608], g_xs_l[8388608];   // x [8192,1024]
__device__ __align__(16) __nv_bfloat16 g_wq_h[3145728], g_wq_l[3145728];   // Wqkv [3072,1024]
__device__ __align__(16) __nv_bfloat16 g_qt_h[8388608], g_qt_l[8388608];   // Qp^T [4][1024,2048]
__device__ __align__(16) __nv_bfloat16 g_kt_h[8388608], g_kt_l[8388608];   // Kp^T
__device__ __align__(16) __nv_bfloat16 g_vt_h[8388608], g_vt_l[8388608];   // v^T
__device__ __align__(16) __nv_bfloat16 g_xt_h[8388608], g_xt_l[8388608];   // x^T
__device__ __align__(16) __nv_bfloat16 g_wt_h[8388608], g_wt_l[8388608];   // (WOp)^T
__device__ __align__(16) __nv_bfloat16 g_m1_h[4194304], g_m1_l[4194304];   // M1
__device__ __align__(16) __nv_bfloat16 g_m2_h[4194304], g_m2_l[4194304];   // M2^T
__device__ __align__(16) __nv_bfloat16 g_m3_h[4194304], g_m3_l[4194304];   // M3^T
__device__ __align__(16) __nv_bfloat16 g_t1_h[4194304], g_t1_l[4194304];   // T1
__device__ __align__(16) __nv_bfloat16 g_t2_h[4194304], g_t2_l[4194304];   // T2^T

// ======================= PTX helpers (sm_80-class only) ====================
__device__ __forceinline__ uint32_t smem_u32(const void* p) {
    uint32_t a;
    asm("{ .reg .u64 t; cvta.to.shared.u64 t, %1; cvt.u32.u64 %0, t; }"
        : "=r"(a) : "l"(p));
    return a;
}
#define CP16(dst, src) \
    asm volatile("cp.async.cg.shared.global [%0], [%1], 16;" :: "r"(dst), "l"(src))
#define CP_COMMIT() asm volatile("cp.async.commit_group;" ::: "memory")
#define CP_WAIT1()  asm volatile("cp.async.wait_group 1;" ::: "memory")

__device__ __forceinline__ void ldsm4(uint32_t* r, uint32_t addr) {
    asm volatile("ldmatrix.sync.aligned.m8n8.x4.shared.b16 {%0,%1,%2,%3}, [%4];"
        : "=r"(r[0]), "=r"(r[1]), "=r"(r[2]), "=r"(r[3]) : "r"(addr));
}
__device__ __forceinline__ void mma16816(float* d, const uint32_t* a,
                                         uint32_t b0, uint32_t b1) {
    asm volatile(
        "mma.sync.aligned.m16n8k16.row.col.f32.bf16.bf16.f32 "
        "{%0,%1,%2,%3}, {%4,%5,%6,%7}, {%8,%9}, {%0,%1,%2,%3};"
        : "+f"(d[0]), "+f"(d[1]), "+f"(d[2]), "+f"(d[3])
        : "r"(a[0]), "r"(a[1]), "r"(a[2]), "r"(a[3]), "r"(b0), "r"(b1));
}

// ======================= split converters ==================================
union Pack8 { unsigned short u[8]; uint4 v; };

__device__ __forceinline__ void split8(const float* f, uint4& hv, uint4& lv) {
    Pack8 h, l;
    #pragma unroll
    for (int j = 0; j < 8; j++) {
        float v = f[j];
        __nv_bfloat16 bh = __float2bfloat16(v);
        float rem = v - __bfloat162float(bh);
        __nv_bfloat16 bl = __float2bfloat16(rem);
        h.u[j] = *(unsigned short*)&bh;
        l.u[j] = *(unsigned short*)&bl;
    }
    hv = h.v; lv = l.v;
}

// K-major source -> row-major bf16 hi/lo
__global__ __launch_bounds__(256) void split_k(
    const float* __restrict__ src, __nv_bfloat16* __restrict__ dh,
    __nv_bfloat16* __restrict__ dl, int K8,
    long long srcStride, long long dstStride)
{
    int idx = blockIdx.x * 256 + threadIdx.x;
    int z = blockIdx.y;
    int r = idx / K8, g = idx - r * K8;
    const float* sp = src + z * srcStride + (size_t)r * (K8 * 8) + g * 8;
    float f[8];
    *(float4*)(f)     = *(const float4*)(sp);
    *(float4*)(f + 4) = *(const float4*)(sp + 4);
    uint4 hv, lv; split8(f, hv, lv);
    size_t off = z * dstStride + (size_t)r * (K8 * 8) + g * 8;
    *(uint4*)(dh + off) = hv;
    *(uint4*)(dl + off) = lv;
}

// Transposed source: out[r][k] = src[k*ldkSrc + r] * (scale?[k]); out ld = Kld
__global__ __launch_bounds__(256) void split_t(
    const float* __restrict__ src, const float* __restrict__ scale,
    __nv_bfloat16* __restrict__ dh, __nv_bfloat16* __restrict__ dl,
    int ldkSrc, int Kld, long long srcStride, int scaleStride, long long dstStride)
{
    __shared__ float t[64][132];
    int z = blockIdx.z;
    int k0 = blockIdx.x * 64, r0 = blockIdx.y * 128;
    int tid = threadIdx.x;
    int rr = tid & 127, kk = tid >> 7;
    const float* sp = src + z * srcStride;
    const float* sc = scale ? scale + (size_t)z * scaleStride : nullptr;
    for (int k = kk; k < 64; k += 2) {
        float v = sp[(size_t)(k0 + k) * ldkSrc + r0 + rr];
        if (sc) v *= sc[k0 + k];
        t[k][rr] = v;
    }
    __syncthreads();
    #pragma unroll
    for (int q = 0; q < 4; q++) {
        int task = tid + 256 * q;          // 1024 tasks: 128 rows x 8 col-groups
        int r = task >> 3, c8 = task & 7;
        float f[8];
        #pragma unroll
        for (int j = 0; j < 8; j++) f[j] = t[c8 * 8 + j][r];
        uint4 hv, lv; split8(f, hv, lv);
        size_t off = z * dstStride + (size_t)(r0 + r) * Kld + k0 + c8 * 8;
        *(uint4*)(dh + off) = hv;
        *(uint4*)(dl + off) = lv;
    }
}

// ======================= bf16-split HMMA GEMM ==============================
// C[M,N] = alpha * (A_f32 . B_f32^T) + bias, A/B given as bf16 hi/lo pairs,
// 3-segment K concat: A=[hi|lo|hi], B=[hi|hi|lo]. Row-major, ld = K.
// CTA tile 128x128, 256 thr (8 warps, warp tile 32x64), BK=32, 3-stage cp.async.
#define AROWB 80                       // 64B data + 16B pad (conflict-free ldsm)
#define ATILEB (128 * AROWB)           // 10240
#define STGB (2 * ATILEB)              // 20480
#define NSTAGE 3
#define GEMM_SMEM (NSTAGE * STGB)      // 61440

__global__ __launch_bounds__(256) void gemm_mma(
    const __nv_bfloat16* __restrict__ Ahi, const __nv_bfloat16* __restrict__ Alo,
    const __nv_bfloat16* __restrict__ Bhi, const __nv_bfloat16* __restrict__ Blo,
    const float* __restrict__ bias, float* __restrict__ C,
    int K, int ldc, float alpha,
    long long aStr, long long bStr, long long cStr)
{
    extern __shared__ char smem[];
    uint32_t sb = smem_u32(smem);
    const int tid = threadIdx.x, lane = tid & 31, w = tid >> 5;
    const int wm = w & 3, wn = w >> 2;          // 4x2 warp grid
    const int m0 = blockIdx.y * 128, n0 = blockIdx.x * 128, z = blockIdx.z;
    const __nv_bfloat16* Aseg[3] = { Ahi + z * aStr, Alo + z * aStr, Ahi + z * aStr };
    const __nv_bfloat16* Bseg[3] = { Bhi + z * bStr, Bhi + z * bStr, Blo + z * bStr };
    const int cps = K >> 5;                      // chunks per segment
    const int C3 = 3 * cps;

    auto issue = [&](int c) {
        int st = c - (c / NSTAGE) * NSTAGE;
        int seg = c / cps, bk = (c - seg * cps) << 5;
        uint32_t ab = sb + st * STGB, bb = ab + ATILEB;
        const __nv_bfloat16* As = Aseg[seg];
        const __nv_bfloat16* Bs = Bseg[seg];
        #pragma unroll
        for (int h = 0; h < 2; h++) {
            int id = tid + h * 256;
            int r = id >> 2, cc = id & 3;
            CP16(ab + r * AROWB + cc * 16, As + (size_t)(m0 + r) * K + bk + cc * 8);
            CP16(bb + r * AROWB + cc * 16, Bs + (size_t)(n0 + r) * K + bk + cc * 8);
        }
        CP_COMMIT();
    };
    issue(0);
    issue(1);

    float d[2][8][4];
    #pragma unroll
    for (int i = 0; i < 2; i++)
        #pragma unroll
        for (int j = 0; j < 8; j++)
            #pragma unroll
            for (int q = 0; q < 4; q++) d[i][j][q] = 0.0f;

    for (int c = 0; c < C3; c++) {
        CP_WAIT1();
        __syncthreads();
        if (c + 2 < C3) issue(c + 2); else CP_COMMIT();
        int st = c - (c / NSTAGE) * NSTAGE;
        uint32_t ab = sb + st * STGB, bb = ab + ATILEB;
        #pragma unroll
        for (int ks = 0; ks < 2; ks++) {
            uint32_t colB = ks * 32 + ((lane >> 4) << 4);
            uint32_t ar[2][4], br[4][4];
            #pragma unroll
            for (int mt = 0; mt < 2; mt++)
                ldsm4(ar[mt], ab + (wm * 32 + mt * 16 + (lane & 15)) * AROWB + colB);
            #pragma unroll
            for (int ng = 0; ng < 4; ng++)
                ldsm4(br[ng], bb + (wn * 64 + ng * 16 + (lane & 15)) * AROWB + colB);
            #pragma unroll
            for (int mt = 0; mt < 2; mt++)
                #pragma unroll
                for (int ng = 0; ng < 4; ng++) {
                    mma16816(d[mt][2 * ng],     ar[mt], br[ng][0], br[ng][2]);
                    mma16816(d[mt][2 * ng + 1], ar[mt], br[ng][1], br[ng][3]);
                }
        }
        __syncthreads();
    }

    // epilogue
    const int gr = lane >> 2, qc = lane & 3;
    float* Cb = C + (size_t)z * cStr;
    #pragma unroll
    for (int mt = 0; mt < 2; mt++) {
        #pragma unroll
        for (int nt = 0; nt < 8; nt++) {
            int mrow = m0 + wm * 32 + mt * 16 + gr;
            int ncol = n0 + wn * 64 + nt * 8 + qc * 2;
            float b0 = 0.0f, b1 = 0.0f;
            if (bias) { float2 bv = *(const float2*)(bias + ncol); b0 = bv.x; b1 = bv.y; }
            float2 v0 = make_float2(d[mt][nt][0] * alpha + b0, d[mt][nt][1] * alpha + b1);
            float2 v1 = make_float2(d[mt][nt][2] * alpha + b0, d[mt][nt][3] * alpha + b1);
            *(float2*)(Cb + (size_t)mrow * ldc + ncol) = v0;
            *(float2*)(Cb + (size_t)(mrow + 8) * ldc + ncol) = v1;
        }
    }
}

// ======================= pruning pipeline (R5, proven) =====================
__global__ void zero_k()
{
    int i = blockIdx.x * 256 + threadIdx.x;
    if (i < 8 * HBINS) g_hist[i] = 0;
    if (i < 8) { g_ccnt[i] = 0; g_below[i] = 0; }
}

__global__ void norms_hist_k()
{
    int idx = blockIdx.x * 256 + threadIdx.x;
    int b = idx >> 19;
    int r = idx & (NTILES - 1);
    int s2 = r >> 9, d2 = r & 511;
    size_t base = ((size_t)(b * SB + 2 * s2)) * F3 + 2 * d2;
    #pragma unroll
    for (int qk = 0; qk < 2; qk++) {
        size_t p = base + qk * EB;
        float2 a = *(const float2*)&g_qkv[p];
        float2 c = *(const float2*)&g_qkv[p + F3];
        float s00 = __fmul_rn(a.x, a.x);
        float s01 = __fmul_rn(a.y, a.y);
        float s10 = __fmul_rn(c.x, c.x);
        float s11 = __fmul_rn(c.y, c.y);
        float nm = sqrtf(__fadd_rn(__fadd_rn(__fadd_rn(s00, s01), s10), s11));
        if (qk == 0) g_normq[idx] = nm; else g_normk[idx] = nm;
        int bin = (int)(nm * 1024.0f);
        if (bin < 0) bin = 0;
        if (bin > HBINS - 1) bin = HBINS - 1;
        atomicAdd(&g_hist[(qk * 4 + b) * HBINS + bin], 1u);
    }
}

__global__ __launch_bounds__(256) void approx_median_k()
{
    __shared__ unsigned part[256];
    int g = blockIdx.x, tid = threadIdx.x;
    const unsigned* h = &g_hist[g * HBINS];
    unsigned s = 0;
    for (int i = tid * 32; i < tid * 32 + 32; i++) s += h[i];
    part[tid] = s;
    __syncthreads();
    if (tid == 0) {
        unsigned k = 262143, cum = 0;
        int seg = 0;
        while (seg < 256 && cum + part[seg] <= k) { cum += part[seg]; seg++; }
        int bin = seg * 32;
        while (true) { unsigned c = h[bin]; if (cum + c > k) break; cum += c; bin++; }
        g_thra[g] = ((float)bin + 0.5f) * (1.0f / 1024.0f);
    }
}

__global__ void candidates_k()
{
    int idx = blockIdx.x * 256 + threadIdx.x;
    int b = idx >> 19;
    int r = idx & (NTILES - 1);
    #pragma unroll
    for (int qk = 0; qk < 2; qk++) {
        float nm = qk ? g_normk[idx] : g_normq[idx];
        int g = qk * 4 + b;
        float d = nm - g_thra[g];
        if (fabsf(d) <= DELTA) {
            unsigned pos = atomicAdd(&g_ccnt[g], 1u);
            if (pos < CAP) g_cidx[g * CAP + pos] = r;
        } else if (d < 0.0f) {
            atomicAdd(&g_below[g], 1u);
        }
    }
}

__device__ __forceinline__ float comp_dot(
    const float* __restrict__ a, const float* __restrict__ b, float bias)
{
    float s = 0.0f, c = 0.0f;
    for (int k = 0; k < EB; k++) {
        float av = a[k], bv = b[k];
        float p = __fmul_rn(av, bv);
        float e = __fmaf_rn(av, bv, -p);
        float t = __fadd_rn(s, p);
        float z = (fabsf(s) >= fabsf(p))
                  ? __fadd_rn(__fadd_rn(s, -t), p)
                  : __fadd_rn(__fadd_rn(p, -t), s);
        c = __fadd_rn(c, __fadd_rn(z, e));
        s = t;
    }
    float v = __fadd_rn(s, c);
    return __fadd_rn(v, bias);
}

__global__ void exact_dots_k(const float* __restrict__ x,
                             const float* __restrict__ Wqkv,
                             const float* __restrict__ bqkv)
{
    int flat = blockIdx.x * 256 + threadIdx.x;
    int e    = flat & 3;
    int cand = (flat >> 2) & (CAP - 1);
    int g    = flat >> 16;
    if (g >= 8) return;
    unsigned cnt = g_ccnt[g]; if (cnt > CAP) cnt = CAP;
    if ((unsigned)cand >= cnt) return;
    int r  = g_cidx[g * CAP + cand];
    int qk = g >> 2, b = g & 3;
    int s2 = r >> 9, d2 = r & 511;
    int srow = 2 * s2 + (e >> 1);
    int dcol = 2 * d2 + (e & 1) + qk * EB;
    float v = comp_dot(x + ((size_t)(b * SB + srow)) * EB,
                       Wqkv + (size_t)dcol * EB, bqkv[dcol]);
    g_cval[(size_t)(g * CAP + cand) * 4 + e] = v;
}

__global__ void exact_norm_k()
{
    int flat = blockIdx.x * 256 + threadIdx.x;
    int cand = flat & (CAP - 1);
    int g    = flat >> 14;
    if (g >= 8) return;
    unsigned cnt = g_ccnt[g]; if (cnt > CAP) cnt = CAP;
    if ((unsigned)cand >= cnt) return;
    const float* v = &g_cval[(size_t)(g * CAP + cand) * 4];
    float s00 = __fmul_rn(v[0], v[0]);
    float s01 = __fmul_rn(v[1], v[1]);
    float s10 = __fmul_rn(v[2], v[2]);
    float s11 = __fmul_rn(v[3], v[3]);
    float nm = sqrtf(__fadd_rn(__fadd_rn(__fadd_rn(s00, s01), s10), s11));
    g_cnorm[g * CAP + cand] = nm;
    int r = g_cidx[g * CAP + cand];
    int b = g & 3;
    if ((g >> 2) == 0) g_normq[b * NTILES + r] = nm;
    else               g_normk[b * NTILES + r] = nm;
}

__global__ __launch_bounds__(1024) void cand_select_k()
{
    __shared__ float s_v1, s_v2;
    int g = blockIdx.x;
    unsigned cnt = g_ccnt[g]; if (cnt > CAP) cnt = CAP;
    long long below = (long long)g_below[g];
    long long r1 = 262143LL - below;
    long long r2 = 262144LL - below;
    const float* cn = &g_cnorm[g * CAP];
    for (unsigned i = threadIdx.x; i < cnt; i += 1024) {
        float v = cn[i];
        long long less = 0, eq = 0;
        for (unsigned j = 0; j < cnt; j++) {
            float w = cn[j];
            less += (w < v);
            eq   += (w == v);
        }
        if (less <= r1 && r1 < less + eq) s_v1 = v;
        if (less <= r2 && r2 < less + eq) s_v2 = v;
    }
    __syncthreads();
    if (threadIdx.x == 0)
        g_thr[g] = __fmul_rn(0.5f, __fadd_rn(s_v1, s_v2));
}

__global__ void mask_tiles2_k()
{
    int idx = blockIdx.x * 256 + threadIdx.x;
    int b = idx >> 19;
    int r = idx & (NTILES - 1);
    int s2 = r >> 9, d2 = r & 511;
    size_t base = ((size_t)(b * SB + 2 * s2)) * F3 + 2 * d2;
    float2 z = make_float2(0.0f, 0.0f);
    if (g_normq[idx] < g_thr[b]) {
        *(float2*)&g_qkv[base]      = z;
        *(float2*)&g_qkv[base + F3] = z;
    }
    if (g_normk[idx] < g_thr[4 + b]) {
        *(float2*)&g_qkv[base + EB]      = z;
        *(float2*)&g_qkv[base + EB + F3] = z;
    }
}

__global__ void wo_rownorm_k(const float* __restrict__ WO)
{
    int warp = threadIdx.x >> 5, lane = threadIdx.x & 31;
    int row = blockIdx.x * 8 + warp;
    const float* p = WO + (size_t)row * EB;
    float s = 0.0f, c = 0.0f;
    for (int d = lane; d < EB; d += 32) {
        float v = p[d];
        float pr = __fmul_rn(v, v);
        float e  = __fmaf_rn(v, v, -pr);
        float t  = __fadd_rn(s, pr);
        float z  = (fabsf(s) >= fabsf(pr))
                   ? __fadd_rn(__fadd_rn(s, -t), pr)
                   : __fadd_rn(__fadd_rn(pr, -t), s);
        c = __fadd_rn(c, __fadd_rn(z, e));
        s = t;
    }
    float tot_s = s, tot_c = c;
    #pragma unroll
    for (int o = 16; o; o >>= 1) {
        float os = __shfl_xor_sync(0xffffffffu, tot_s, o);
        float oc = __shfl_xor_sync(0xffffffffu, tot_c, o);
        float t = __fadd_rn(tot_s, os);
        float z = (fabsf(tot_s) >= fabsf(os))
                  ? __fadd_rn(__fadd_rn(tot_s, -t), os)
                  : __fadd_rn(__fadd_rn(os, -t), tot_s);
        tot_c = __fadd_rn(__fadd_rn(tot_c, oc), z);
        tot_s = t;
    }
    if (lane == 0) g_rnorm[row] = sqrtf(__fadd_rn(tot_s, tot_c));
}

__global__ __launch_bounds__(1024) void select_median_k(
    const float* __restrict__ data, int N, int k1, int k2, float* __restrict__ out)
{
    __shared__ unsigned hist[256];
    __shared__ unsigned s_prefix, s_pmask;
    __shared__ int s_k;
    __shared__ float s_v[2];
    const float* d = data + (size_t)blockIdx.x * N;
    const int tid = threadIdx.x;
    for (int which = 0; which < 2; which++) {
        int k = which ? k2 : k1;
        unsigned prefix = 0, pmask = 0;
        for (int pass = 0; pass < 4; pass++) {
            int shift = 24 - 8 * pass;
            if (tid < 256) hist[tid] = 0;
            __syncthreads();
            for (int i = tid; i < N; i += 1024) {
                unsigned u = __float_as_uint(d[i]);
                if ((u & pmask) == prefix) atomicAdd(&hist[(u >> shift) & 255], 1u);
            }
            __syncthreads();
            if (tid == 0) {
                int cum = 0, bin = 0;
                for (; bin < 256; bin++) {
                    int cc = (int)hist[bin];
                    if (cum + cc > k) break;
                    cum += cc;
                }
                s_prefix = prefix | ((unsigned)bin << shift);
                s_pmask  = pmask  | (255u << shift);
                s_k = k - cum;
            }
            __syncthreads();
            prefix = s_prefix; pmask = s_pmask; k = s_k;
        }
        if (tid == 0) s_v[which] = __uint_as_float(prefix);
        __syncthreads();
    }
    if (tid == 0) out[blockIdx.x] = __fmul_rn(0.5f, __fadd_rn(s_v[0], s_v[1]));
}

__global__ void wmask_k()
{
    int idx = blockIdx.x * 256 + threadIdx.x;
    int b = idx >> 11;
    g_wmask[idx] = (g_rnorm[idx] >= g_thr[8 + b]) ? 1.0f : 0.0f;
}

// ======================= launch ============================================
extern "C" void kernel_launch(void* const* d_in, const int* in_sizes, int n_in,
                              void* d_out, int out_size)
{
    const float* x    = (const float*)d_in[0];
    const float* Wqkv = (const float*)d_in[1];
    const float* bqkv = (const float*)d_in[2];
    const float* WO   = (const float*)d_in[3];
    float* out = (float*)d_out;

    cudaFuncSetAttribute(gemm_mma, cudaFuncAttributeMaxDynamicSharedMemorySize,
                         GEMM_SMEM);

    float *qkv, *rnorm, *thr, *M1, *M2, *M3, *T1, *T2, *wmask;
    cudaGetSymbolAddress((void**)&qkv,   g_qkv);
    cudaGetSymbolAddress((void**)&rnorm, g_rnorm);
    cudaGetSymbolAddress((void**)&thr,   g_thr);
    cudaGetSymbolAddress((void**)&wmask, g_wmask);
    cudaGetSymbolAddress((void**)&M1,    g_M1);
    cudaGetSymbolAddress((void**)&M2,    g_M2);
    cudaGetSymbolAddress((void**)&M3,    g_M3);
    cudaGetSymbolAddress((void**)&T1,    g_T1);
    cudaGetSymbolAddress((void**)&T2,    g_T2);

    __nv_bfloat16 *xs_h, *xs_l, *wq_h, *wq_l, *qt_h, *qt_l, *kt_h, *kt_l;
    __nv_bfloat16 *vt_h, *vt_l, *xt_h, *xt_l, *wt_h, *wt_l;
    __nv_bfloat16 *m1_h, *m1_l, *m2_h, *m2_l, *m3_h, *m3_l;
    __nv_bfloat16 *t1_h, *t1_l, *t2_h, *t2_l;
    cudaGetSymbolAddress((void**)&xs_h, g_xs_h); cudaGetSymbolAddress((void**)&xs_l, g_xs_l);
    cudaGetSymbolAddress((void**)&wq_h, g_wq_h); cudaGetSymbolAddress((void**)&wq_l, g_wq_l);
    cudaGetSymbolAddress((void**)&qt_h, g_qt_h); cudaGetSymbolAddress((void**)&qt_l, g_qt_l);
    cudaGetSymbolAddress((void**)&kt_h, g_kt_h); cudaGetSymbolAddress((void**)&kt_l, g_kt_l);
    cudaGetSymbolAddress((void**)&vt_h, g_vt_h); cudaGetSymbolAddress((void**)&vt_l, g_vt_l);
    cudaGetSymbolAddress((void**)&xt_h, g_xt_h); cudaGetSymbolAddress((void**)&xt_l, g_xt_l);
    cudaGetSymbolAddress((void**)&wt_h, g_wt_h); cudaGetSymbolAddress((void**)&wt_l, g_wt_l);
    cudaGetSymbolAddress((void**)&m1_h, g_m1_h); cudaGetSymbolAddress((void**)&m1_l, g_m1_l);
    cudaGetSymbolAddress((void**)&m2_h, g_m2_h); cudaGetSymbolAddress((void**)&m2_l, g_m2_l);
    cudaGetSymbolAddress((void**)&m3_h, g_m3_h); cudaGetSymbolAddress((void**)&m3_l, g_m3_l);
    cudaGetSymbolAddress((void**)&t1_h, g_t1_h); cudaGetSymbolAddress((void**)&t1_l, g_t1_l);
    cudaGetSymbolAddress((void**)&t2_h, g_t2_h); cudaGetSymbolAddress((void**)&t2_l, g_t2_l);

    const long long sEE = (long long)EB * EB;
    const long long sSE = (long long)SB * EB;
    const long long sQKV = (long long)SB * F3;

    // 0) counters
    zero_k<<<(8 * HBINS + 255) / 256, 256>>>();

    // 1) input splits + qkv GEMM (fp32 out, +bias)
    split_k<<<dim3(4096, 1), 256>>>(x, xs_h, xs_l, 128, 0, 0);
    split_k<<<dim3(1536, 1), 256>>>(Wqkv, wq_h, wq_l, 128, 0, 0);
    gemm_mma<<<dim3(24, 64, 1), 256, GEMM_SMEM>>>(
        xs_h, xs_l, wq_h, wq_l, bqkv, qkv, EB, F3, 1.0f, 0, 0, 0);

    // 2) tile pruning, lazy-exact boundary resolution (thresholds bit-exact)
    norms_hist_k<<<8192, 256>>>();
    approx_median_k<<<8, 256>>>();
    candidates_k<<<8192, 256>>>();
    exact_dots_k<<<8 * CAP * 4 / 256, 256>>>(x, Wqkv, bqkv);
    exact_norm_k<<<8 * CAP / 256, 256>>>();
    cand_select_k<<<8, 1024>>>();
    mask_tiles2_k<<<8192, 256>>>();

    // 3) WO row pruning
    wo_rownorm_k<<<1024, 256>>>(WO);
    select_median_k<<<NB, 1024>>>(rnorm, SB, 1023, 1024, thr + 8);
    wmask_k<<<32, 256>>>();

    // 4) transposed splits of chain operands (row-major [R,K])
    split_t<<<dim3(32, 8, NB), 256>>>(qkv,          nullptr, qt_h, qt_l, F3, SB, sQKV, 0, sSE);
    split_t<<<dim3(32, 8, NB), 256>>>(qkv + EB,     nullptr, kt_h, kt_l, F3, SB, sQKV, 0, sSE);
    split_t<<<dim3(32, 8, NB), 256>>>(qkv + 2 * EB, nullptr, vt_h, vt_l, F3, SB, sQKV, 0, sSE);
    split_t<<<dim3(32, 8, NB), 256>>>(x,            nullptr, xt_h, xt_l, EB, SB, sSE, 0, sSE);
    split_t<<<dim3(32, 8, NB), 256>>>(WO,           wmask,   wt_h, wt_l, EB, SB, sSE, SB, sSE);

    // 5) chain GEMMs: out = x * [ (1/32 Qp^T Kp)(x^T v)(WOp^T x) ]
    dim3 gE(8, 8, NB);
    gemm_mma<<<gE, 256, GEMM_SMEM>>>(qt_h, qt_l, kt_h, kt_l, nullptr, M1,
                                     SB, EB, 1.0f / 32.0f, sSE, sSE, sEE);
    gemm_mma<<<gE, 256, GEMM_SMEM>>>(xt_h, xt_l, vt_h, vt_l, nullptr, M2,
                                     SB, EB, 1.0f, sSE, sSE, sEE);
    gemm_mma<<<gE, 256, GEMM_SMEM>>>(wt_h, wt_l, xt_h, xt_l, nullptr, M3,
                                     SB, EB, 1.0f, sSE, sSE, sEE);
    split_k<<<dim3(512, NB), 256>>>(M1, m1_h, m1_l, 128, sEE, sEE);
    split_t<<<dim3(16, 8, NB), 256>>>(M2, nullptr, m2_h, m2_l, EB, EB, sEE, 0, sEE);
    gemm_mma<<<gE, 256, GEMM_SMEM>>>(m1_h, m1_l, m2_h, m2_l, nullptr, T1,
                                     EB, EB, 1.0f, sEE, sEE, sEE);
    split_k<<<dim3(512, NB), 256>>>(T1, t1_h, t1_l, 128, sEE, sEE);
    split_t<<<dim3(16, 8, NB), 256>>>(M3, nullptr, m3_h, m3_l, EB, EB, sEE, 0, sEE);
    gemm_mma<<<gE, 256, GEMM_SMEM>>>(t1_h, t1_l, m3_h, m3_l, nullptr, T2,
                                     EB, EB, 1.0f, sEE, sEE, sEE);
    split_t<<<dim3(16, 8, NB), 256>>>(T2, nullptr, t2_h, t2_l, EB, EB, sEE, 0, sEE);
    gemm_mma<<<dim3(8, 16, NB), 256, GEMM_SMEM>>>(xs_h, xs_l, t2_h, t2_l, nullptr, out,
                                                  EB, EB, 1.0f, sSE, sEE, sSE);
}

// round 10
// speedup vs baseline: 2.1741x; 1.0059x over previous
#include <cuda_runtime.h>
#include <cuda_bf16.h>
#include <math.h>
#include <stdint.h>

// Problem constants
#define SB 2048
#define EB 1024
#define NB 4
#define F3 3072
#define NTILES 524288
#define CAP 16384
#define HBINS 8192
#define DELTA 2.5e-3f

// ---------------- scratch (device globals) ---------------------------------
__device__ float g_qkv[NB * SB * F3];
__device__ float g_normq[NB * NTILES];
__device__ float g_normk[NB * NTILES];
__device__ float g_rnorm[NB * SB];
__device__ float g_thr[12];
__device__ float g_thra[8];
__device__ float g_wmask[NB * SB];
__device__ unsigned g_hist[8 * HBINS];
__device__ unsigned g_ccnt[8];
__device__ unsigned g_below[8];
__device__ int   g_cidx[8 * CAP];
__device__ float g_cval[8 * CAP * 4];
__device__ float g_cnorm[8 * CAP];
__device__ float g_M1[NB * EB * EB];
__device__ float g_M2[NB * EB * EB];      // holds M2^T
__device__ float g_M3[NB * EB * EB];      // holds M3^T
__device__ float g_T1[NB * EB * EB];
__device__ float g_T2[NB * EB * EB];      // holds T2^T

// bf16 split operands (plain row-major, ld = K)
__device__ __align__(16) __nv_bfloat16 g_xs_h[8388608], g_xs_l[8388608];   // x [8192,1024]
__device__ __align__(16) __nv_bfloat16 g_wq_h[3145728], g_wq_l[3145728];   // Wqkv
__device__ __align__(16) __nv_bfloat16 g_qt_h[8388608], g_qt_l[8388608];   // Qp^T
__device__ __align__(16) __nv_bfloat16 g_kt_h[8388608], g_kt_l[8388608];   // Kp^T
__device__ __align__(16) __nv_bfloat16 g_vt_h[8388608], g_vt_l[8388608];   // v^T
__device__ __align__(16) __nv_bfloat16 g_xt_h[8388608], g_xt_l[8388608];   // x^T
__device__ __align__(16) __nv_bfloat16 g_wt_h[8388608], g_wt_l[8388608];   // WOp^T
__device__ __align__(16) __nv_bfloat16 g_m1_h[4194304], g_m1_l[4194304];   // M1
__device__ __align__(16) __nv_bfloat16 g_m2_h[4194304], g_m2_l[4194304];   // M2^T
__device__ __align__(16) __nv_bfloat16 g_m3_h[4194304], g_m3_l[4194304];   // M3^T
__device__ __align__(16) __nv_bfloat16 g_t1_h[4194304], g_t1_l[4194304];   // T1
__device__ __align__(16) __nv_bfloat16 g_t2_h[4194304], g_t2_l[4194304];   // T2^T

// ======================= PTX helpers (sm_80-class only) ====================
__device__ __forceinline__ uint32_t smem_u32(const void* p) {
    uint32_t a;
    asm("{ .reg .u64 t; cvta.to.shared.u64 t, %1; cvt.u32.u64 %0, t; }"
        : "=r"(a) : "l"(p));
    return a;
}
#define CP16(dst, src) \
    asm volatile("cp.async.cg.shared.global [%0], [%1], 16;" :: "r"(dst), "l"(src))
#define CP_COMMIT() asm volatile("cp.async.commit_group;" ::: "memory")
#define CP_WAIT2()  asm volatile("cp.async.wait_group 2;" ::: "memory")

__device__ __forceinline__ void ldsm4(uint32_t* r, uint32_t addr) {
    asm volatile("ldmatrix.sync.aligned.m8n8.x4.shared.b16 {%0,%1,%2,%3}, [%4];"
        : "=r"(r[0]), "=r"(r[1]), "=r"(r[2]), "=r"(r[3]) : "r"(addr));
}
__device__ __forceinline__ void mma16816(float* d, const uint32_t* a,
                                         uint32_t b0, uint32_t b1) {
    asm volatile(
        "mma.sync.aligned.m16n8k16.row.col.f32.bf16.bf16.f32 "
        "{%0,%1,%2,%3}, {%4,%5,%6,%7}, {%8,%9}, {%0,%1,%2,%3};"
        : "+f"(d[0]), "+f"(d[1]), "+f"(d[2]), "+f"(d[3])
        : "r"(a[0]), "r"(a[1]), "r"(a[2]), "r"(a[3]), "r"(b0), "r"(b1));
}

// ======================= split converters ==================================
union Pack8 { unsigned short u[8]; uint4 v; };

__device__ __forceinline__ void split8(const float* f, uint4& hv, uint4& lv) {
    Pack8 h, l;
    #pragma unroll
    for (int j = 0; j < 8; j++) {
        float v = f[j];
        __nv_bfloat16 bh = __float2bfloat16(v);
        float rem = v - __bfloat162float(bh);
        __nv_bfloat16 bl = __float2bfloat16(rem);
        h.u[j] = *(unsigned short*)&bh;
        l.u[j] = *(unsigned short*)&bl;
    }
    hv = h.v; lv = l.v;
}

// K-major (row-major) source -> row-major bf16 hi/lo
__global__ __launch_bounds__(256) void split_k(
    const float* __restrict__ src, __nv_bfloat16* __restrict__ dh,
    __nv_bfloat16* __restrict__ dl, int K8,
    long long srcStride, long long dstStride)
{
    int idx = blockIdx.x * 256 + threadIdx.x;
    int z = blockIdx.y;
    int r = idx / K8, g = idx - r * K8;
    const float* sp = src + z * srcStride + (size_t)r * (K8 * 8) + g * 8;
    float f[8];
    *(float4*)(f)     = *(const float4*)(sp);
    *(float4*)(f + 4) = *(const float4*)(sp + 4);
    uint4 hv, lv; split8(f, hv, lv);
    size_t off = z * dstStride + (size_t)r * (K8 * 8) + g * 8;
    *(uint4*)(dh + off) = hv;
    *(uint4*)(dl + off) = lv;
}

// Transposed source: out[r][k] = src[k*ldkSrc + r] * (scale?[k]); out ld = Kld
__global__ __launch_bounds__(256) void split_t(
    const float* __restrict__ src, const float* __restrict__ scale,
    __nv_bfloat16* __restrict__ dh, __nv_bfloat16* __restrict__ dl,
    int ldkSrc, int Kld, long long srcStride, int scaleStride, long long dstStride)
{
    __shared__ float t[64][132];
    int z = blockIdx.z;
    int k0 = blockIdx.x * 64, r0 = blockIdx.y * 128;
    int tid = threadIdx.x;
    int rr = tid & 127, kk = tid >> 7;
    const float* sp = src + z * srcStride;
    const float* sc = scale ? scale + (size_t)z * scaleStride : nullptr;
    for (int k = kk; k < 64; k += 2) {
        float v = sp[(size_t)(k0 + k) * ldkSrc + r0 + rr];
        if (sc) v *= sc[k0 + k];
        t[k][rr] = v;
    }
    __syncthreads();
    #pragma unroll
    for (int q = 0; q < 4; q++) {
        int task = tid + 256 * q;
        int r = task >> 3, c8 = task & 7;
        float f[8];
        #pragma unroll
        for (int j = 0; j < 8; j++) f[j] = t[c8 * 8 + j][r];
        uint4 hv, lv; split8(f, hv, lv);
        size_t off = z * dstStride + (size_t)(r0 + r) * Kld + k0 + c8 * 8;
        *(uint4*)(dh + off) = hv;
        *(uint4*)(dl + off) = lv;
    }
}

// ======================= bf16-split HMMA GEMM (v2: 4-stage, 1 sync) ========
// C[M,N] = alpha * (A_f32 . B_f32^T) + bias, 3-segment K concat:
// A=[hi|lo|hi], B=[hi|hi|lo].
#define AROWB 80
#define ATILEB (128 * AROWB)
#define STGB (2 * ATILEB)
#define NSTAGE 4
#define GEMM_SMEM (NSTAGE * STGB)      // 81920

__global__ __launch_bounds__(256, 2) void gemm_mma(
    const __nv_bfloat16* __restrict__ Ahi, const __nv_bfloat16* __restrict__ Alo,
    const __nv_bfloat16* __restrict__ Bhi, const __nv_bfloat16* __restrict__ Blo,
    const float* __restrict__ bias, float* __restrict__ C,
    int K, int ldc, float alpha,
    long long aStr, long long bStr, long long cStr)
{
    extern __shared__ char smem[];
    uint32_t sb = smem_u32(smem);
    const int tid = threadIdx.x, lane = tid & 31, w = tid >> 5;
    const int wm = w & 3, wn = w >> 2;
    const int m0 = blockIdx.y * 128, n0 = blockIdx.x * 128, z = blockIdx.z;
    const __nv_bfloat16* Aseg[3] = { Ahi + z * aStr, Alo + z * aStr, Ahi + z * aStr };
    const __nv_bfloat16* Bseg[3] = { Bhi + z * bStr, Bhi + z * bStr, Blo + z * bStr };
    const int cps = K >> 5;
    const int C3 = 3 * cps;

    auto issue = [&](int c) {
        int st = c & (NSTAGE - 1);
        int seg = c / cps, bk = (c - seg * cps) << 5;
        uint32_t ab = sb + st * STGB, bb = ab + ATILEB;
        const __nv_bfloat16* As = Aseg[seg];
        const __nv_bfloat16* Bs = Bseg[seg];
        #pragma unroll
        for (int h = 0; h < 2; h++) {
            int id = tid + h * 256;
            int r = id >> 2, cc = id & 3;
            CP16(ab + r * AROWB + cc * 16, As + (size_t)(m0 + r) * K + bk + cc * 8);
            CP16(bb + r * AROWB + cc * 16, Bs + (size_t)(n0 + r) * K + bk + cc * 8);
        }
        CP_COMMIT();
    };
    issue(0); issue(1); issue(2);

    float d[2][8][4];
    #pragma unroll
    for (int i = 0; i < 2; i++)
        #pragma unroll
        for (int j = 0; j < 8; j++)
            #pragma unroll
            for (int q = 0; q < 4; q++) d[i][j][q] = 0.0f;

    for (int c = 0; c < C3; c++) {
        CP_WAIT2();
        __syncthreads();
        if (c + 3 < C3) issue(c + 3); else CP_COMMIT();
        int st = c & (NSTAGE - 1);
        uint32_t ab = sb + st * STGB, bb = ab + ATILEB;
        #pragma unroll
        for (int ks = 0; ks < 2; ks++) {
            uint32_t colB = ks * 32 + ((lane >> 4) << 4);
            uint32_t ar[2][4], br[4][4];
            #pragma unroll
            for (int mt = 0; mt < 2; mt++)
                ldsm4(ar[mt], ab + (wm * 32 + mt * 16 + (lane & 15)) * AROWB + colB);
            #pragma unroll
            for (int ng = 0; ng < 4; ng++)
                ldsm4(br[ng], bb + (wn * 64 + ng * 16 + (lane & 15)) * AROWB + colB);
            #pragma unroll
            for (int mt = 0; mt < 2; mt++)
                #pragma unroll
                for (int ng = 0; ng < 4; ng++) {
                    mma16816(d[mt][2 * ng],     ar[mt], br[ng][0], br[ng][2]);
                    mma16816(d[mt][2 * ng + 1], ar[mt], br[ng][1], br[ng][3]);
                }
        }
    }

    // epilogue
    const int gr = lane >> 2, qc = lane & 3;
    float* Cb = C + (size_t)z * cStr;
    #pragma unroll
    for (int mt = 0; mt < 2; mt++) {
        #pragma unroll
        for (int nt = 0; nt < 8; nt++) {
            int mrow = m0 + wm * 32 + mt * 16 + gr;
            int ncol = n0 + wn * 64 + nt * 8 + qc * 2;
            float b0 = 0.0f, b1 = 0.0f;
            if (bias) { float2 bv = *(const float2*)(bias + ncol); b0 = bv.x; b1 = bv.y; }
            float2 v0 = make_float2(d[mt][nt][0] * alpha + b0, d[mt][nt][1] * alpha + b1);
            float2 v1 = make_float2(d[mt][nt][2] * alpha + b0, d[mt][nt][3] * alpha + b1);
            *(float2*)(Cb + (size_t)mrow * ldc + ncol) = v0;
            *(float2*)(Cb + (size_t)(mrow + 8) * ldc + ncol) = v1;
        }
    }
}

// ======================= pruning pipeline (proven) =========================
__global__ void zero_k()
{
    int i = blockIdx.x * 256 + threadIdx.x;
    if (i < 8 * HBINS) g_hist[i] = 0;
    if (i < 8) { g_ccnt[i] = 0; g_below[i] = 0; }
}

__global__ void norms_hist_k()
{
    int idx = blockIdx.x * 256 + threadIdx.x;
    int b = idx >> 19;
    int r = idx & (NTILES - 1);
    int s2 = r >> 9, d2 = r & 511;
    size_t base = ((size_t)(b * SB + 2 * s2)) * F3 + 2 * d2;
    #pragma unroll
    for (int qk = 0; qk < 2; qk++) {
        size_t p = base + qk * EB;
        float2 a = *(const float2*)&g_qkv[p];
        float2 c = *(const float2*)&g_qkv[p + F3];
        float s00 = __fmul_rn(a.x, a.x);
        float s01 = __fmul_rn(a.y, a.y);
        float s10 = __fmul_rn(c.x, c.x);
        float s11 = __fmul_rn(c.y, c.y);
        float nm = sqrtf(__fadd_rn(__fadd_rn(__fadd_rn(s00, s01), s10), s11));
        if (qk == 0) g_normq[idx] = nm; else g_normk[idx] = nm;
        int bin = (int)(nm * 1024.0f);
        if (bin < 0) bin = 0;
        if (bin > HBINS - 1) bin = HBINS - 1;
        atomicAdd(&g_hist[(qk * 4 + b) * HBINS + bin], 1u);
    }
}

__global__ __launch_bounds__(256) void approx_median_k()
{
    __shared__ unsigned part[256];
    int g = blockIdx.x, tid = threadIdx.x;
    const unsigned* h = &g_hist[g * HBINS];
    unsigned s = 0;
    for (int i = tid * 32; i < tid * 32 + 32; i++) s += h[i];
    part[tid] = s;
    __syncthreads();
    if (tid == 0) {
        unsigned k = 262143, cum = 0;
        int seg = 0;
        while (seg < 256 && cum + part[seg] <= k) { cum += part[seg]; seg++; }
        int bin = seg * 32;
        while (true) { unsigned c = h[bin]; if (cum + c > k) break; cum += c; bin++; }
        g_thra[g] = ((float)bin + 0.5f) * (1.0f / 1024.0f);
    }
}

__global__ void candidates_k()
{
    int idx = blockIdx.x * 256 + threadIdx.x;
    int b = idx >> 19;
    int r = idx & (NTILES - 1);
    #pragma unroll
    for (int qk = 0; qk < 2; qk++) {
        float nm = qk ? g_normk[idx] : g_normq[idx];
        int g = qk * 4 + b;
        float d = nm - g_thra[g];
        if (fabsf(d) <= DELTA) {
            unsigned pos = atomicAdd(&g_ccnt[g], 1u);
            if (pos < CAP) g_cidx[g * CAP + pos] = r;
        } else if (d < 0.0f) {
            atomicAdd(&g_below[g], 1u);
        }
    }
}

__device__ __forceinline__ float comp_dot(
    const float* __restrict__ a, const float* __restrict__ b, float bias)
{
    float s = 0.0f, c = 0.0f;
    for (int k = 0; k < EB; k++) {
        float av = a[k], bv = b[k];
        float p = __fmul_rn(av, bv);
        float e = __fmaf_rn(av, bv, -p);
        float t = __fadd_rn(s, p);
        float z = (fabsf(s) >= fabsf(p))
                  ? __fadd_rn(__fadd_rn(s, -t), p)
                  : __fadd_rn(__fadd_rn(p, -t), s);
        c = __fadd_rn(c, __fadd_rn(z, e));
        s = t;
    }
    float v = __fadd_rn(s, c);
    return __fadd_rn(v, bias);
}

__global__ void exact_dots_k(const float* __restrict__ x,
                             const float* __restrict__ Wqkv,
                             const float* __restrict__ bqkv)
{
    int flat = blockIdx.x * 256 + threadIdx.x;
    int e    = flat & 3;
    int cand = (flat >> 2) & (CAP - 1);
    int g    = flat >> 16;
    if (g >= 8) return;
    unsigned cnt = g_ccnt[g]; if (cnt > CAP) cnt = CAP;
    if ((unsigned)cand >= cnt) return;
    int r  = g_cidx[g * CAP + cand];
    int qk = g >> 2, b = g & 3;
    int s2 = r >> 9, d2 = r & 511;
    int srow = 2 * s2 + (e >> 1);
    int dcol = 2 * d2 + (e & 1) + qk * EB;
    float v = comp_dot(x + ((size_t)(b * SB + srow)) * EB,
                       Wqkv + (size_t)dcol * EB, bqkv[dcol]);
    g_cval[(size_t)(g * CAP + cand) * 4 + e] = v;
}

__global__ void exact_norm_k()
{
    int flat = blockIdx.x * 256 + threadIdx.x;
    int cand = flat & (CAP - 1);
    int g    = flat >> 14;
    if (g >= 8) return;
    unsigned cnt = g_ccnt[g]; if (cnt > CAP) cnt = CAP;
    if ((unsigned)cand >= cnt) return;
    const float* v = &g_cval[(size_t)(g * CAP + cand) * 4];
    float s00 = __fmul_rn(v[0], v[0]);
    float s01 = __fmul_rn(v[1], v[1]);
    float s10 = __fmul_rn(v[2], v[2]);
    float s11 = __fmul_rn(v[3], v[3]);
    float nm = sqrtf(__fadd_rn(__fadd_rn(__fadd_rn(s00, s01), s10), s11));
    g_cnorm[g * CAP + cand] = nm;
    int r = g_cidx[g * CAP + cand];
    int b = g & 3;
    if ((g >> 2) == 0) g_normq[b * NTILES + r] = nm;
    else               g_normk[b * NTILES + r] = nm;
}

__global__ __launch_bounds__(1024) void cand_select_k()
{
    __shared__ float s_v1, s_v2;
    int g = blockIdx.x;
    unsigned cnt = g_ccnt[g]; if (cnt > CAP) cnt = CAP;
    long long below = (long long)g_below[g];
    long long r1 = 262143LL - below;
    long long r2 = 262144LL - below;
    const float* cn = &g_cnorm[g * CAP];
    for (unsigned i = threadIdx.x; i < cnt; i += 1024) {
        float v = cn[i];
        long long less = 0, eq = 0;
        for (unsigned j = 0; j < cnt; j++) {
            float w = cn[j];
            less += (w < v);
            eq   += (w == v);
        }
        if (less <= r1 && r1 < less + eq) s_v1 = v;
        if (less <= r2 && r2 < less + eq) s_v2 = v;
    }
    __syncthreads();
    if (threadIdx.x == 0)
        g_thr[g] = __fmul_rn(0.5f, __fadd_rn(s_v1, s_v2));
}

__global__ void mask_tiles2_k()
{
    int idx = blockIdx.x * 256 + threadIdx.x;
    int b = idx >> 19;
    int r = idx & (NTILES - 1);
    int s2 = r >> 9, d2 = r & 511;
    size_t base = ((size_t)(b * SB + 2 * s2)) * F3 + 2 * d2;
    float2 z = make_float2(0.0f, 0.0f);
    if (g_normq[idx] < g_thr[b]) {
        *(float2*)&g_qkv[base]      = z;
        *(float2*)&g_qkv[base + F3] = z;
    }
    if (g_normk[idx] < g_thr[4 + b]) {
        *(float2*)&g_qkv[base + EB]      = z;
        *(float2*)&g_qkv[base + EB + F3] = z;
    }
}

__global__ void wo_rownorm_k(const float* __restrict__ WO)
{
    int warp = threadIdx.x >> 5, lane = threadIdx.x & 31;
    int row = blockIdx.x * 8 + warp;
    const float* p = WO + (size_t)row * EB;
    float s = 0.0f, c = 0.0f;
    for (int d = lane; d < EB; d += 32) {
        float v = p[d];
        float pr = __fmul_rn(v, v);
        float e  = __fmaf_rn(v, v, -pr);
        float t  = __fadd_rn(s, pr);
        float z  = (fabsf(s) >= fabsf(pr))
                   ? __fadd_rn(__fadd_rn(s, -t), pr)
                   : __fadd_rn(__fadd_rn(pr, -t), s);
        c = __fadd_rn(c, __fadd_rn(z, e));
        s = t;
    }
    float tot_s = s, tot_c = c;
    #pragma unroll
    for (int o = 16; o; o >>= 1) {
        float os = __shfl_xor_sync(0xffffffffu, tot_s, o);
        float oc = __shfl_xor_sync(0xffffffffu, tot_c, o);
        float t = __fadd_rn(tot_s, os);
        float z = (fabsf(tot_s) >= fabsf(os))
                  ? __fadd_rn(__fadd_rn(tot_s, -t), os)
                  : __fadd_rn(__fadd_rn(os, -t), tot_s);
        tot_c = __fadd_rn(__fadd_rn(tot_c, oc), z);
        tot_s = t;
    }
    if (lane == 0) g_rnorm[row] = sqrtf(__fadd_rn(tot_s, tot_c));
}

__global__ __launch_bounds__(1024) void select_median_k(
    const float* __restrict__ data, int N, int k1, int k2, float* __restrict__ out)
{
    __shared__ unsigned hist[256];
    __shared__ unsigned s_prefix, s_pmask;
    __shared__ int s_k;
    __shared__ float s_v[2];
    const float* d = data + (size_t)blockIdx.x * N;
    const int tid = threadIdx.x;
    for (int which = 0; which < 2; which++) {
        int k = which ? k2 : k1;
        unsigned prefix = 0, pmask = 0;
        for (int pass = 0; pass < 4; pass++) {
            int shift = 24 - 8 * pass;
            if (tid < 256) hist[tid] = 0;
            __syncthreads();
            for (int i = tid; i < N; i += 1024) {
                unsigned u = __float_as_uint(d[i]);
                if ((u & pmask) == prefix) atomicAdd(&hist[(u >> shift) & 255], 1u);
            }
            __syncthreads();
            if (tid == 0) {
                int cum = 0, bin = 0;
                for (; bin < 256; bin++) {
                    int cc = (int)hist[bin];
                    if (cum + cc > k) break;
                    cum += cc;
                }
                s_prefix = prefix | ((unsigned)bin << shift);
                s_pmask  = pmask  | (255u << shift);
                s_k = k - cum;
            }
            __syncthreads();
            prefix = s_prefix; pmask = s_pmask; k = s_k;
        }
        if (tid == 0) s_v[which] = __uint_as_float(prefix);
        __syncthreads();
    }
    if (tid == 0) out[blockIdx.x] = __fmul_rn(0.5f, __fadd_rn(s_v[0], s_v[1]));
}

__global__ void wmask_k()
{
    int idx = blockIdx.x * 256 + threadIdx.x;
    int b = idx >> 11;
    g_wmask[idx] = (g_rnorm[idx] >= g_thr[8 + b]) ? 1.0f : 0.0f;
}

// ======================= launch (single stream, capture-safe) ==============
extern "C" void kernel_launch(void* const* d_in, const int* in_sizes, int n_in,
                              void* d_out, int out_size)
{
    const float* x    = (const float*)d_in[0];
    const float* Wqkv = (const float*)d_in[1];
    const float* bqkv = (const float*)d_in[2];
    const float* WO   = (const float*)d_in[3];
    float* out = (float*)d_out;

    cudaFuncSetAttribute(gemm_mma, cudaFuncAttributeMaxDynamicSharedMemorySize,
                         GEMM_SMEM);

    float *qkv, *rnorm, *thr, *M1, *M2t, *M3t, *T1, *T2t, *wmask;
    cudaGetSymbolAddress((void**)&qkv,   g_qkv);
    cudaGetSymbolAddress((void**)&rnorm, g_rnorm);
    cudaGetSymbolAddress((void**)&thr,   g_thr);
    cudaGetSymbolAddress((void**)&wmask, g_wmask);
    cudaGetSymbolAddress((void**)&M1,    g_M1);
    cudaGetSymbolAddress((void**)&M2t,   g_M2);
    cudaGetSymbolAddress((void**)&M3t,   g_M3);
    cudaGetSymbolAddress((void**)&T1,    g_T1);
    cudaGetSymbolAddress((void**)&T2t,   g_T2);

    __nv_bfloat16 *xs_h, *xs_l, *wq_h, *wq_l, *qt_h, *qt_l, *kt_h, *kt_l;
    __nv_bfloat16 *vt_h, *vt_l, *xt_h, *xt_l, *wt_h, *wt_l;
    __nv_bfloat16 *m1_h, *m1_l, *m2_h, *m2_l, *m3_h, *m3_l;
    __nv_bfloat16 *t1_h, *t1_l, *t2_h, *t2_l;
    cudaGetSymbolAddress((void**)&xs_h, g_xs_h); cudaGetSymbolAddress((void**)&xs_l, g_xs_l);
    cudaGetSymbolAddress((void**)&wq_h, g_wq_h); cudaGetSymbolAddress((void**)&wq_l, g_wq_l);
    cudaGetSymbolAddress((void**)&qt_h, g_qt_h); cudaGetSymbolAddress((void**)&qt_l, g_qt_l);
    cudaGetSymbolAddress((void**)&kt_h, g_kt_h); cudaGetSymbolAddress((void**)&kt_l, g_kt_l);
    cudaGetSymbolAddress((void**)&vt_h, g_vt_h); cudaGetSymbolAddress((void**)&vt_l, g_vt_l);
    cudaGetSymbolAddress((void**)&xt_h, g_xt_h); cudaGetSymbolAddress((void**)&xt_l, g_xt_l);
    cudaGetSymbolAddress((void**)&wt_h, g_wt_h); cudaGetSymbolAddress((void**)&wt_l, g_wt_l);
    cudaGetSymbolAddress((void**)&m1_h, g_m1_h); cudaGetSymbolAddress((void**)&m1_l, g_m1_l);
    cudaGetSymbolAddress((void**)&m2_h, g_m2_h); cudaGetSymbolAddress((void**)&m2_l, g_m2_l);
    cudaGetSymbolAddress((void**)&m3_h, g_m3_h); cudaGetSymbolAddress((void**)&m3_l, g_m3_l);
    cudaGetSymbolAddress((void**)&t1_h, g_t1_h); cudaGetSymbolAddress((void**)&t1_l, g_t1_l);
    cudaGetSymbolAddress((void**)&t2_h, g_t2_h); cudaGetSymbolAddress((void**)&t2_l, g_t2_l);

    const long long sEE = (long long)EB * EB;
    const long long sSE = (long long)SB * EB;
    const long long sQKV = (long long)SB * F3;
    dim3 gE(8, 8, NB);

    // 0) counters + input splits
    zero_k<<<(8 * HBINS + 255) / 256, 256>>>();
    split_k<<<dim3(4096, 1), 256>>>(x, xs_h, xs_l, 128, 0, 0);
    split_k<<<dim3(1536, 1), 256>>>(Wqkv, wq_h, wq_l, 128, 0, 0);

    // 1) qkv GEMM (fp32 out, +bias)
    gemm_mma<<<dim3(24, 64, 1), 256, GEMM_SMEM>>>(
        xs_h, xs_l, wq_h, wq_l, bqkv, qkv, EB, F3, 1.0f, 0, 0, 0);

    // 2) tile pruning, lazy-exact boundary resolution (thresholds bit-exact)
    norms_hist_k<<<8192, 256>>>();
    approx_median_k<<<8, 256>>>();
    candidates_k<<<8192, 256>>>();
    exact_dots_k<<<8 * CAP * 4 / 256, 256>>>(x, Wqkv, bqkv);
    exact_norm_k<<<8 * CAP / 256, 256>>>();
    cand_select_k<<<8, 1024>>>();
    mask_tiles2_k<<<8192, 256>>>();

    // 3) WO row pruning
    wo_rownorm_k<<<1024, 256>>>(WO);
    select_median_k<<<NB, 1024>>>(rnorm, SB, 1023, 1024, thr + 8);
    wmask_k<<<32, 256>>>();

    // 4) transposed splits of S-K operands ([R=1024 rows, K=2048])
    split_t<<<dim3(32, 8, NB), 256>>>(qkv,          nullptr, qt_h, qt_l, F3, SB, sQKV, 0, sSE);
    split_t<<<dim3(32, 8, NB), 256>>>(qkv + EB,     nullptr, kt_h, kt_l, F3, SB, sQKV, 0, sSE);
    split_t<<<dim3(32, 8, NB), 256>>>(qkv + 2 * EB, nullptr, vt_h, vt_l, F3, SB, sQKV, 0, sSE);
    split_t<<<dim3(32, 8, NB), 256>>>(x,            nullptr, xt_h, xt_l, EB, SB, sSE, 0, sSE);
    split_t<<<dim3(32, 8, NB), 256>>>(WO,           wmask,   wt_h, wt_l, EB, SB, sSE, SB, sSE);

    // 5) chain with output swapping (gemm(A,B) = A.B^T):
    //    M1   = (1/32) Qp^T Kp        = gemm(qt, kt)
    //    M2^T = v^T x                 = gemm(vt, xt)
    //    M3^T = x^T WOp               = gemm(xt, wt)
    //    T1   = M1.M2 = M1.(M2^T)^T   = gemm(m1, m2t)
    //    T2^T = M3^T.T1^T             = gemm(m3t, t1)
    //    out  = x.T2 = x.(T2^T)^T     = gemm(xs, t2t)
    gemm_mma<<<gE, 256, GEMM_SMEM>>>(qt_h, qt_l, kt_h, kt_l, nullptr, M1,
                                     SB, EB, 1.0f / 32.0f, sSE, sSE, sEE);
    gemm_mma<<<gE, 256, GEMM_SMEM>>>(vt_h, vt_l, xt_h, xt_l, nullptr, M2t,
                                     SB, EB, 1.0f, sSE, sSE, sEE);
    gemm_mma<<<gE, 256, GEMM_SMEM>>>(xt_h, xt_l, wt_h, wt_l, nullptr, M3t,
                                     SB, EB, 1.0f, sSE, sSE, sEE);
    split_k<<<dim3(512, NB), 256>>>(M1,  m1_h, m1_l, 128, sEE, sEE);
    split_k<<<dim3(512, NB), 256>>>(M2t, m2_h, m2_l, 128, sEE, sEE);
    split_k<<<dim3(512, NB), 256>>>(M3t, m3_h, m3_l, 128, sEE, sEE);
    gemm_mma<<<gE, 256, GEMM_SMEM>>>(m1_h, m1_l, m2_h, m2_l, nullptr, T1,
                                     EB, EB, 1.0f, sEE, sEE, sEE);
    split_k<<<dim3(512, NB), 256>>>(T1, t1_h, t1_l, 128, sEE, sEE);
    gemm_mma<<<gE, 256, GEMM_SMEM>>>(m3_h, m3_l, t1_h, t1_l, nullptr, T2t,
                                     EB, EB, 1.0f, sEE, sEE, sEE);
    split_k<<<dim3(512, NB), 256>>>(T2t, t2_h, t2_l, 128, sEE, sEE);
    gemm_mma<<<dim3(8, 16, NB), 256, GEMM_SMEM>>>(xs_h, xs_l, t2_h, t2_l, nullptr, out,
                                                  EB, EB, 1.0f, sSE, sEE, sSE);
}

// round 11
// speedup vs baseline: 2.2042x; 1.0139x over previous
#include <cuda_runtime.h>
#include <cuda_bf16.h>
#include <math.h>
#include <stdint.h>

// Problem constants
#define SB 2048
#define EB 1024
#define NB 4
#define F3 3072
#define NTILES 524288
#define CAP 16384
#define HBINS 8192
#define DELTA 2.5e-3f

// ---------------- scratch (device globals) ---------------------------------
__device__ float g_qkv[NB * SB * F3];
__device__ float g_normq[NB * NTILES];
__device__ float g_normk[NB * NTILES];
__device__ float g_rnorm[NB * SB];
__device__ float g_thr[12];
__device__ float g_thra[8];
__device__ float g_wmask[NB * SB];
__device__ unsigned g_hist[8 * HBINS];
__device__ unsigned g_ccnt[8];
__device__ unsigned g_below[8];
__device__ int   g_cidx[8 * CAP];
__device__ float g_cval[8 * CAP * 4];
__device__ float g_cnorm[8 * CAP];

// bf16 split operands (plain row-major, ld = K)
__device__ __align__(16) __nv_bfloat16 g_xs_h[8388608], g_xs_l[8388608];   // x [8192,1024]
__device__ __align__(16) __nv_bfloat16 g_wq_h[3145728], g_wq_l[3145728];   // Wqkv
__device__ __align__(16) __nv_bfloat16 g_qt_h[8388608], g_qt_l[8388608];   // Qp^T
__device__ __align__(16) __nv_bfloat16 g_kt_h[8388608], g_kt_l[8388608];   // Kp^T
__device__ __align__(16) __nv_bfloat16 g_vt_h[8388608], g_vt_l[8388608];   // v^T
__device__ __align__(16) __nv_bfloat16 g_xt_h[8388608], g_xt_l[8388608];   // x^T
__device__ __align__(16) __nv_bfloat16 g_wt_h[8388608], g_wt_l[8388608];   // WOp^T
__device__ __align__(16) __nv_bfloat16 g_m1_h[4194304], g_m1_l[4194304];   // M1
__device__ __align__(16) __nv_bfloat16 g_m2_h[4194304], g_m2_l[4194304];   // M2^T
__device__ __align__(16) __nv_bfloat16 g_m3_h[4194304], g_m3_l[4194304];   // M3^T
__device__ __align__(16) __nv_bfloat16 g_t1_h[4194304], g_t1_l[4194304];   // T1
__device__ __align__(16) __nv_bfloat16 g_t2_h[4194304], g_t2_l[4194304];   // T2^T

// ======================= PTX helpers =======================================
__device__ __forceinline__ uint32_t smem_u32(const void* p) {
    uint32_t a;
    asm("{ .reg .u64 t; cvta.to.shared.u64 t, %1; cvt.u32.u64 %0, t; }"
        : "=r"(a) : "l"(p));
    return a;
}
#define CP16(dst, src) \
    asm volatile("cp.async.cg.shared.global [%0], [%1], 16;" :: "r"(dst), "l"(src))
#define CP_COMMIT() asm volatile("cp.async.commit_group;" ::: "memory")
#define CP_WAIT2()  asm volatile("cp.async.wait_group 2;" ::: "memory")

__device__ __forceinline__ void ldsm4(uint32_t* r, uint32_t addr) {
    asm volatile("ldmatrix.sync.aligned.m8n8.x4.shared.b16 {%0,%1,%2,%3}, [%4];"
        : "=r"(r[0]), "=r"(r[1]), "=r"(r[2]), "=r"(r[3]) : "r"(addr));
}
__device__ __forceinline__ void mma16816(float* d, const uint32_t* a,
                                         uint32_t b0, uint32_t b1) {
    asm volatile(
        "mma.sync.aligned.m16n8k16.row.col.f32.bf16.bf16.f32 "
        "{%0,%1,%2,%3}, {%4,%5,%6,%7}, {%8,%9}, {%0,%1,%2,%3};"
        : "+f"(d[0]), "+f"(d[1]), "+f"(d[2]), "+f"(d[3])
        : "r"(a[0]), "r"(a[1]), "r"(a[2]), "r"(a[3]), "r"(b0), "r"(b1));
}

// ======================= split helpers =====================================
union Pack8 { unsigned short u[8]; uint4 v; };

__device__ __forceinline__ void split8(const float* f, uint4& hv, uint4& lv) {
    Pack8 h, l;
    #pragma unroll
    for (int j = 0; j < 8; j++) {
        float v = f[j];
        __nv_bfloat16 bh = __float2bfloat16(v);
        float rem = v - __bfloat162float(bh);
        __nv_bfloat16 bl = __float2bfloat16(rem);
        h.u[j] = *(unsigned short*)&bh;
        l.u[j] = *(unsigned short*)&bl;
    }
    hv = h.v; lv = l.v;
}

__device__ __forceinline__ void split2(float v0, float v1,
                                       uint32_t& hw, uint32_t& lw) {
    __nv_bfloat16 h0 = __float2bfloat16(v0);
    __nv_bfloat16 h1 = __float2bfloat16(v1);
    float r0 = v0 - __bfloat162float(h0);
    float r1 = v1 - __bfloat162float(h1);
    __nv_bfloat16 l0 = __float2bfloat16(r0);
    __nv_bfloat16 l1 = __float2bfloat16(r1);
    hw = (uint32_t)(*(unsigned short*)&h0) | ((uint32_t)(*(unsigned short*)&h1) << 16);
    lw = (uint32_t)(*(unsigned short*)&l0) | ((uint32_t)(*(unsigned short*)&l1) << 16);
}

// K-major (row-major) source -> row-major bf16 hi/lo
__global__ __launch_bounds__(256) void split_k(
    const float* __restrict__ src, __nv_bfloat16* __restrict__ dh,
    __nv_bfloat16* __restrict__ dl, int K8,
    long long srcStride, long long dstStride)
{
    int idx = blockIdx.x * 256 + threadIdx.x;
    int z = blockIdx.y;
    int r = idx / K8, g = idx - r * K8;
    const float* sp = src + z * srcStride + (size_t)r * (K8 * 8) + g * 8;
    float f[8];
    *(float4*)(f)     = *(const float4*)(sp);
    *(float4*)(f + 4) = *(const float4*)(sp + 4);
    uint4 hv, lv; split8(f, hv, lv);
    size_t off = z * dstStride + (size_t)r * (K8 * 8) + g * 8;
    *(uint4*)(dh + off) = hv;
    *(uint4*)(dl + off) = lv;
}

// Fused transposed splits: 5 ops x NB batches, z = op*NB + b.
// out[r][k] = src[k*ldkSrc + r] * (scale?[k]); out ld = SB, dstStride = SB*EB.
struct SOp {
    const float* src;
    const float* scale;
    __nv_bfloat16* dh;
    __nv_bfloat16* dl;
    int ldkSrc;
    long long srcStride;
    int scaleStride;
};

__global__ __launch_bounds__(256) void split_t5(SOp o0, SOp o1, SOp o2, SOp o3, SOp o4)
{
    __shared__ float t[64][132];
    int zb = blockIdx.z;
    int opi = zb >> 2, z = zb & 3;
    SOp op = (opi == 0) ? o0 : (opi == 1) ? o1 : (opi == 2) ? o2 : (opi == 3) ? o3 : o4;
    int k0 = blockIdx.x * 64, r0 = blockIdx.y * 128;
    int tid = threadIdx.x;
    int rr = tid & 127, kk = tid >> 7;
    const float* sp = op.src + z * op.srcStride;
    const float* sc = op.scale ? op.scale + (size_t)z * op.scaleStride : nullptr;
    for (int k = kk; k < 64; k += 2) {
        float v = sp[(size_t)(k0 + k) * op.ldkSrc + r0 + rr];
        if (sc) v *= sc[k0 + k];
        t[k][rr] = v;
    }
    __syncthreads();
    const long long dstStride = (long long)SB * EB;
    #pragma unroll
    for (int q = 0; q < 4; q++) {
        int task = tid + 256 * q;
        int r = task >> 3, c8 = task & 7;
        float f[8];
        #pragma unroll
        for (int j = 0; j < 8; j++) f[j] = t[c8 * 8 + j][r];
        uint4 hv, lv; split8(f, hv, lv);
        size_t off = z * dstStride + (size_t)(r0 + r) * SB + k0 + c8 * 8;
        *(uint4*)(op.dh + off) = hv;
        *(uint4*)(op.dl + off) = lv;
    }
}

// ======================= bf16-split HMMA GEMM core =========================
// C = A_f32 . B_f32^T, 3-segment K concat: A=[hi|lo|hi], B=[hi|hi|lo].
#define AROWB 80
#define ATILEB (128 * AROWB)
#define STGB (2 * ATILEB)
#define NSTAGE 4
#define GEMM_SMEM (NSTAGE * STGB)      // 81920

__device__ __forceinline__ void gemm_core(
    uint32_t sb, int tid,
    const __nv_bfloat16* __restrict__ Ahi, const __nv_bfloat16* __restrict__ Alo,
    const __nv_bfloat16* __restrict__ Bhi, const __nv_bfloat16* __restrict__ Blo,
    int K, int m0, int n0, float (&d)[2][8][4])
{
    const int lane = tid & 31, w = tid >> 5;
    const int wm = w & 3, wn = w >> 2;
    const __nv_bfloat16* Aseg[3] = { Ahi, Alo, Ahi };
    const __nv_bfloat16* Bseg[3] = { Bhi, Bhi, Blo };
    const int cps = K >> 5;
    const int C3 = 3 * cps;

    auto issue = [&](int c) {
        int st = c & (NSTAGE - 1);
        int seg = c / cps, bk = (c - seg * cps) << 5;
        uint32_t ab = sb + st * STGB, bb = ab + ATILEB;
        const __nv_bfloat16* As = Aseg[seg];
        const __nv_bfloat16* Bs = Bseg[seg];
        #pragma unroll
        for (int h = 0; h < 2; h++) {
            int id = tid + h * 256;
            int r = id >> 2, cc = id & 3;
            CP16(ab + r * AROWB + cc * 16, As + (size_t)(m0 + r) * K + bk + cc * 8);
            CP16(bb + r * AROWB + cc * 16, Bs + (size_t)(n0 + r) * K + bk + cc * 8);
        }
        CP_COMMIT();
    };
    issue(0); issue(1); issue(2);

    #pragma unroll
    for (int i = 0; i < 2; i++)
        #pragma unroll
        for (int j = 0; j < 8; j++)
            #pragma unroll
            for (int q = 0; q < 4; q++) d[i][j][q] = 0.0f;

    for (int c = 0; c < C3; c++) {
        CP_WAIT2();
        __syncthreads();
        if (c + 3 < C3) issue(c + 3); else CP_COMMIT();
        int st = c & (NSTAGE - 1);
        uint32_t ab = sb + st * STGB, bb = ab + ATILEB;
        #pragma unroll
        for (int ks = 0; ks < 2; ks++) {
            uint32_t colB = ks * 32 + ((lane >> 4) << 4);
            uint32_t ar[2][4], br[4][4];
            #pragma unroll
            for (int mt = 0; mt < 2; mt++)
                ldsm4(ar[mt], ab + (wm * 32 + mt * 16 + (lane & 15)) * AROWB + colB);
            #pragma unroll
            for (int ng = 0; ng < 4; ng++)
                ldsm4(br[ng], bb + (wn * 64 + ng * 16 + (lane & 15)) * AROWB + colB);
            #pragma unroll
            for (int mt = 0; mt < 2; mt++)
                #pragma unroll
                for (int ng = 0; ng < 4; ng++) {
                    mma16816(d[mt][2 * ng],     ar[mt], br[ng][0], br[ng][2]);
                    mma16816(d[mt][2 * ng + 1], ar[mt], br[ng][1], br[ng][3]);
                }
        }
    }
}

// fp32 epilogue GEMM (qkv with bias; final out)
__global__ __launch_bounds__(256, 2) void gemm_mma(
    const __nv_bfloat16* __restrict__ Ahi, const __nv_bfloat16* __restrict__ Alo,
    const __nv_bfloat16* __restrict__ Bhi, const __nv_bfloat16* __restrict__ Blo,
    const float* __restrict__ bias, float* __restrict__ C,
    int K, int ldc, float alpha,
    long long aStr, long long bStr, long long cStr)
{
    extern __shared__ char smem[];
    uint32_t sb = smem_u32(smem);
    const int tid = threadIdx.x, lane = tid & 31, w = tid >> 5;
    const int wm = w & 3, wn = w >> 2;
    const int m0 = blockIdx.y * 128, n0 = blockIdx.x * 128, z = blockIdx.z;
    float d[2][8][4];
    gemm_core(sb, tid, Ahi + z * aStr, Alo + z * aStr,
              Bhi + z * bStr, Blo + z * bStr, K, m0, n0, d);

    const int gr = lane >> 2, qc = lane & 3;
    float* Cb = C + (size_t)z * cStr;
    #pragma unroll
    for (int mt = 0; mt < 2; mt++) {
        #pragma unroll
        for (int nt = 0; nt < 8; nt++) {
            int mrow = m0 + wm * 32 + mt * 16 + gr;
            int ncol = n0 + wn * 64 + nt * 8 + qc * 2;
            float b0 = 0.0f, b1 = 0.0f;
            if (bias) { float2 bv = *(const float2*)(bias + ncol); b0 = bv.x; b1 = bv.y; }
            float2 v0 = make_float2(d[mt][nt][0] * alpha + b0, d[mt][nt][1] * alpha + b1);
            float2 v1 = make_float2(d[mt][nt][2] * alpha + b0, d[mt][nt][3] * alpha + b1);
            *(float2*)(Cb + (size_t)mrow * ldc + ncol) = v0;
            *(float2*)(Cb + (size_t)(mrow + 8) * ldc + ncol) = v1;
        }
    }
}

// split epilogue: write hi/lo bf16 directly (no fp32 intermediate)
__device__ __forceinline__ void epilogue_split(
    int tid, int m0, int n0, float (&d)[2][8][4], float alpha,
    __nv_bfloat16* __restrict__ Ch, __nv_bfloat16* __restrict__ Cl, int ldc)
{
    const int lane = tid & 31, w = tid >> 5;
    const int wm = w & 3, wn = w >> 2;
    const int gr = lane >> 2, qc = lane & 3;
    #pragma unroll
    for (int mt = 0; mt < 2; mt++) {
        #pragma unroll
        for (int nt = 0; nt < 8; nt++) {
            int mrow = m0 + wm * 32 + mt * 16 + gr;
            int ncol = n0 + wn * 64 + nt * 8 + qc * 2;
            uint32_t hw, lw;
            split2(d[mt][nt][0] * alpha, d[mt][nt][1] * alpha, hw, lw);
            *(uint32_t*)(Ch + (size_t)mrow * ldc + ncol) = hw;
            *(uint32_t*)(Cl + (size_t)mrow * ldc + ncol) = lw;
            split2(d[mt][nt][2] * alpha, d[mt][nt][3] * alpha, hw, lw);
            *(uint32_t*)(Ch + (size_t)(mrow + 8) * ldc + ncol) = hw;
            *(uint32_t*)(Cl + (size_t)(mrow + 8) * ldc + ncol) = lw;
        }
    }
}

// single-op GEMM with split epilogue (T1, T2^T)
__global__ __launch_bounds__(256, 2) void gemm_split(
    const __nv_bfloat16* __restrict__ Ahi, const __nv_bfloat16* __restrict__ Alo,
    const __nv_bfloat16* __restrict__ Bhi, const __nv_bfloat16* __restrict__ Blo,
    __nv_bfloat16* __restrict__ Ch, __nv_bfloat16* __restrict__ Cl,
    int K, int ldc, float alpha,
    long long aStr, long long bStr, long long cStr)
{
    extern __shared__ char smem[];
    uint32_t sb = smem_u32(smem);
    const int tid = threadIdx.x;
    const int m0 = blockIdx.y * 128, n0 = blockIdx.x * 128, z = blockIdx.z;
    float d[2][8][4];
    gemm_core(sb, tid, Ahi + z * aStr, Alo + z * aStr,
              Bhi + z * bStr, Blo + z * bStr, K, m0, n0, d);
    epilogue_split(tid, m0, n0, d, alpha,
                   Ch + (size_t)z * cStr, Cl + (size_t)z * cStr, ldc);
}

// fused 3-op GEMM (M1, M2^T, M3^T), z = op*NB + b, split epilogue
struct GOp {
    const __nv_bfloat16 *Ah, *Al, *Bh, *Bl;
    __nv_bfloat16 *Ch, *Cl;
    float alpha;
};

__global__ __launch_bounds__(256, 2) void gemm3_split(
    GOp o0, GOp o1, GOp o2, int K, int ldc,
    long long aStr, long long bStr, long long cStr)
{
    extern __shared__ char smem[];
    uint32_t sb = smem_u32(smem);
    const int tid = threadIdx.x;
    int zb = blockIdx.z;
    int opi = zb >> 2, z = zb & 3;
    GOp op = (opi == 0) ? o0 : (opi == 1) ? o1 : o2;
    const int m0 = blockIdx.y * 128, n0 = blockIdx.x * 128;
    float d[2][8][4];
    gemm_core(sb, tid, op.Ah + z * aStr, op.Al + z * aStr,
              op.Bh + z * bStr, op.Bl + z * bStr, K, m0, n0, d);
    epilogue_split(tid, m0, n0, d, op.alpha,
                   op.Ch + (size_t)z * cStr, op.Cl + (size_t)z * cStr, ldc);
}

// ======================= pruning pipeline (proven) =========================
__global__ void zero_k()
{
    int i = blockIdx.x * 256 + threadIdx.x;
    if (i < 8 * HBINS) g_hist[i] = 0;
    if (i < 8) { g_ccnt[i] = 0; g_below[i] = 0; }
}

__global__ void norms_hist_k()
{
    int idx = blockIdx.x * 256 + threadIdx.x;
    int b = idx >> 19;
    int r = idx & (NTILES - 1);
    int s2 = r >> 9, d2 = r & 511;
    size_t base = ((size_t)(b * SB + 2 * s2)) * F3 + 2 * d2;
    #pragma unroll
    for (int qk = 0; qk < 2; qk++) {
        size_t p = base + qk * EB;
        float2 a = *(const float2*)&g_qkv[p];
        float2 c = *(const float2*)&g_qkv[p + F3];
        float s00 = __fmul_rn(a.x, a.x);
        float s01 = __fmul_rn(a.y, a.y);
        float s10 = __fmul_rn(c.x, c.x);
        float s11 = __fmul_rn(c.y, c.y);
        float nm = sqrtf(__fadd_rn(__fadd_rn(__fadd_rn(s00, s01), s10), s11));
        if (qk == 0) g_normq[idx] = nm; else g_normk[idx] = nm;
        int bin = (int)(nm * 1024.0f);
        if (bin < 0) bin = 0;
        if (bin > HBINS - 1) bin = HBINS - 1;
        atomicAdd(&g_hist[(qk * 4 + b) * HBINS + bin], 1u);
    }
}

__global__ __launch_bounds__(256) void approx_median_k()
{
    __shared__ unsigned part[256];
    int g = blockIdx.x, tid = threadIdx.x;
    const unsigned* h = &g_hist[g * HBINS];
    unsigned s = 0;
    for (int i = tid * 32; i < tid * 32 + 32; i++) s += h[i];
    part[tid] = s;
    __syncthreads();
    if (tid == 0) {
        unsigned k = 262143, cum = 0;
        int seg = 0;
        while (seg < 256 && cum + part[seg] <= k) { cum += part[seg]; seg++; }
        int bin = seg * 32;
        while (true) { unsigned c = h[bin]; if (cum + c > k) break; cum += c; bin++; }
        g_thra[g] = ((float)bin + 0.5f) * (1.0f / 1024.0f);
    }
}

__global__ void candidates_k()
{
    int idx = blockIdx.x * 256 + threadIdx.x;
    int b = idx >> 19;
    int r = idx & (NTILES - 1);
    #pragma unroll
    for (int qk = 0; qk < 2; qk++) {
        float nm = qk ? g_normk[idx] : g_normq[idx];
        int g = qk * 4 + b;
        float d = nm - g_thra[g];
        if (fabsf(d) <= DELTA) {
            unsigned pos = atomicAdd(&g_ccnt[g], 1u);
            if (pos < CAP) g_cidx[g * CAP + pos] = r;
        } else if (d < 0.0f) {
            atomicAdd(&g_below[g], 1u);
        }
    }
}

__device__ __forceinline__ float comp_dot(
    const float* __restrict__ a, const float* __restrict__ b, float bias)
{
    float s = 0.0f, c = 0.0f;
    for (int k = 0; k < EB; k++) {
        float av = a[k], bv = b[k];
        float p = __fmul_rn(av, bv);
        float e = __fmaf_rn(av, bv, -p);
        float t = __fadd_rn(s, p);
        float z = (fabsf(s) >= fabsf(p))
                  ? __fadd_rn(__fadd_rn(s, -t), p)
                  : __fadd_rn(__fadd_rn(p, -t), s);
        c = __fadd_rn(c, __fadd_rn(z, e));
        s = t;
    }
    float v = __fadd_rn(s, c);
    return __fadd_rn(v, bias);
}

__global__ void exact_dots_k(const float* __restrict__ x,
                             const float* __restrict__ Wqkv,
                             const float* __restrict__ bqkv)
{
    int flat = blockIdx.x * 256 + threadIdx.x;
    int e    = flat & 3;
    int cand = (flat >> 2) & (CAP - 1);
    int g    = flat >> 16;
    if (g >= 8) return;
    unsigned cnt = g_ccnt[g]; if (cnt > CAP) cnt = CAP;
    if ((unsigned)cand >= cnt) return;
    int r  = g_cidx[g * CAP + cand];
    int qk = g >> 2, b = g & 3;
    int s2 = r >> 9, d2 = r & 511;
    int srow = 2 * s2 + (e >> 1);
    int dcol = 2 * d2 + (e & 1) + qk * EB;
    float v = comp_dot(x + ((size_t)(b * SB + srow)) * EB,
                       Wqkv + (size_t)dcol * EB, bqkv[dcol]);
    g_cval[(size_t)(g * CAP + cand) * 4 + e] = v;
}

__global__ void exact_norm_k()
{
    int flat = blockIdx.x * 256 + threadIdx.x;
    int cand = flat & (CAP - 1);
    int g    = flat >> 14;
    if (g >= 8) return;
    unsigned cnt = g_ccnt[g]; if (cnt > CAP) cnt = CAP;
    if ((unsigned)cand >= cnt) return;
    const float* v = &g_cval[(size_t)(g * CAP + cand) * 4];
    float s00 = __fmul_rn(v[0], v[0]);
    float s01 = __fmul_rn(v[1], v[1]);
    float s10 = __fmul_rn(v[2], v[2]);
    float s11 = __fmul_rn(v[3], v[3]);
    float nm = sqrtf(__fadd_rn(__fadd_rn(__fadd_rn(s00, s01), s10), s11));
    g_cnorm[g * CAP + cand] = nm;
    int r = g_cidx[g * CAP + cand];
    int b = g & 3;
    if ((g >> 2) == 0) g_normq[b * NTILES + r] = nm;
    else               g_normk[b * NTILES + r] = nm;
}

__global__ __launch_bounds__(1024) void cand_select_k()
{
    __shared__ float s_v1, s_v2;
    int g = blockIdx.x;
    unsigned cnt = g_ccnt[g]; if (cnt > CAP) cnt = CAP;
    long long below = (long long)g_below[g];
    long long r1 = 262143LL - below;
    long long r2 = 262144LL - below;
    const float* cn = &g_cnorm[g * CAP];
    for (unsigned i = threadIdx.x; i < cnt; i += 1024) {
        float v = cn[i];
        long long less = 0, eq = 0;
        for (unsigned j = 0; j < cnt; j++) {
            float w = cn[j];
            less += (w < v);
            eq   += (w == v);
        }
        if (less <= r1 && r1 < less + eq) s_v1 = v;
        if (less <= r2 && r2 < less + eq) s_v2 = v;
    }
    __syncthreads();
    if (threadIdx.x == 0)
        g_thr[g] = __fmul_rn(0.5f, __fadd_rn(s_v1, s_v2));
}

__global__ void mask_tiles2_k()
{
    int idx = blockIdx.x * 256 + threadIdx.x;
    int b = idx >> 19;
    int r = idx & (NTILES - 1);
    int s2 = r >> 9, d2 = r & 511;
    size_t base = ((size_t)(b * SB + 2 * s2)) * F3 + 2 * d2;
    float2 z = make_float2(0.0f, 0.0f);
    if (g_normq[idx] < g_thr[b]) {
        *(float2*)&g_qkv[base]      = z;
        *(float2*)&g_qkv[base + F3] = z;
    }
    if (g_normk[idx] < g_thr[4 + b]) {
        *(float2*)&g_qkv[base + EB]      = z;
        *(float2*)&g_qkv[base + EB + F3] = z;
    }
}

__global__ void wo_rownorm_k(const float* __restrict__ WO)
{
    int warp = threadIdx.x >> 5, lane = threadIdx.x & 31;
    int row = blockIdx.x * 8 + warp;
    const float* p = WO + (size_t)row * EB;
    float s = 0.0f, c = 0.0f;
    for (int d = lane; d < EB; d += 32) {
        float v = p[d];
        float pr = __fmul_rn(v, v);
        float e  = __fmaf_rn(v, v, -pr);
        float t  = __fadd_rn(s, pr);
        float z  = (fabsf(s) >= fabsf(pr))
                   ? __fadd_rn(__fadd_rn(s, -t), pr)
                   : __fadd_rn(__fadd_rn(pr, -t), s);
        c = __fadd_rn(c, __fadd_rn(z, e));
        s = t;
    }
    float tot_s = s, tot_c = c;
    #pragma unroll
    for (int o = 16; o; o >>= 1) {
        float os = __shfl_xor_sync(0xffffffffu, tot_s, o);
        float oc = __shfl_xor_sync(0xffffffffu, tot_c, o);
        float t = __fadd_rn(tot_s, os);
        float z = (fabsf(tot_s) >= fabsf(os))
                  ? __fadd_rn(__fadd_rn(tot_s, -t), os)
                  : __fadd_rn(__fadd_rn(os, -t), tot_s);
        tot_c = __fadd_rn(__fadd_rn(tot_c, oc), z);
        tot_s = t;
    }
    if (lane == 0) g_rnorm[row] = sqrtf(__fadd_rn(tot_s, tot_c));
}

__global__ __launch_bounds__(1024) void select_median_k(
    const float* __restrict__ data, int N, int k1, int k2, float* __restrict__ out)
{
    __shared__ unsigned hist[256];
    __shared__ unsigned s_prefix, s_pmask;
    __shared__ int s_k;
    __shared__ float s_v[2];
    const float* d = data + (size_t)blockIdx.x * N;
    const int tid = threadIdx.x;
    for (int which = 0; which < 2; which++) {
        int k = which ? k2 : k1;
        unsigned prefix = 0, pmask = 0;
        for (int pass = 0; pass < 4; pass++) {
            int shift = 24 - 8 * pass;
            if (tid < 256) hist[tid] = 0;
            __syncthreads();
            for (int i = tid; i < N; i += 1024) {
                unsigned u = __float_as_uint(d[i]);
                if ((u & pmask) == prefix) atomicAdd(&hist[(u >> shift) & 255], 1u);
            }
            __syncthreads();
            if (tid == 0) {
                int cum = 0, bin = 0;
                for (; bin < 256; bin++) {
                    int cc = (int)hist[bin];
                    if (cum + cc > k) break;
                    cum += cc;
                }
                s_prefix = prefix | ((unsigned)bin << shift);
                s_pmask  = pmask  | (255u << shift);
                s_k = k - cum;
            }
            __syncthreads();
            prefix = s_prefix; pmask = s_pmask; k = s_k;
        }
        if (tid == 0) s_v[which] = __uint_as_float(prefix);
        __syncthreads();
    }
    if (tid == 0) out[blockIdx.x] = __fmul_rn(0.5f, __fadd_rn(s_v[0], s_v[1]));
}

__global__ void wmask_k()
{
    int idx = blockIdx.x * 256 + threadIdx.x;
    int b = idx >> 11;
    g_wmask[idx] = (g_rnorm[idx] >= g_thr[8 + b]) ? 1.0f : 0.0f;
}

// ======================= launch (single stream, capture-safe) ==============
extern "C" void kernel_launch(void* const* d_in, const int* in_sizes, int n_in,
                              void* d_out, int out_size)
{
    const float* x    = (const float*)d_in[0];
    const float* Wqkv = (const float*)d_in[1];
    const float* bqkv = (const float*)d_in[2];
    const float* WO   = (const float*)d_in[3];
    float* out = (float*)d_out;

    cudaFuncSetAttribute(gemm_mma,    cudaFuncAttributeMaxDynamicSharedMemorySize, GEMM_SMEM);
    cudaFuncSetAttribute(gemm_split,  cudaFuncAttributeMaxDynamicSharedMemorySize, GEMM_SMEM);
    cudaFuncSetAttribute(gemm3_split, cudaFuncAttributeMaxDynamicSharedMemorySize, GEMM_SMEM);

    float *qkv, *rnorm, *thr, *wmask;
    cudaGetSymbolAddress((void**)&qkv,   g_qkv);
    cudaGetSymbolAddress((void**)&rnorm, g_rnorm);
    cudaGetSymbolAddress((void**)&thr,   g_thr);
    cudaGetSymbolAddress((void**)&wmask, g_wmask);

    __nv_bfloat16 *xs_h, *xs_l, *wq_h, *wq_l, *qt_h, *qt_l, *kt_h, *kt_l;
    __nv_bfloat16 *vt_h, *vt_l, *xt_h, *xt_l, *wt_h, *wt_l;
    __nv_bfloat16 *m1_h, *m1_l, *m2_h, *m2_l, *m3_h, *m3_l;
    __nv_bfloat16 *t1_h, *t1_l, *t2_h, *t2_l;
    cudaGetSymbolAddress((void**)&xs_h, g_xs_h); cudaGetSymbolAddress((void**)&xs_l, g_xs_l);
    cudaGetSymbolAddress((void**)&wq_h, g_wq_h); cudaGetSymbolAddress((void**)&wq_l, g_wq_l);
    cudaGetSymbolAddress((void**)&qt_h, g_qt_h); cudaGetSymbolAddress((void**)&qt_l, g_qt_l);
    cudaGetSymbolAddress((void**)&kt_h, g_kt_h); cudaGetSymbolAddress((void**)&kt_l, g_kt_l);
    cudaGetSymbolAddress((void**)&vt_h, g_vt_h); cudaGetSymbolAddress((void**)&vt_l, g_vt_l);
    cudaGetSymbolAddress((void**)&xt_h, g_xt_h); cudaGetSymbolAddress((void**)&xt_l, g_xt_l);
    cudaGetSymbolAddress((void**)&wt_h, g_wt_h); cudaGetSymbolAddress((void**)&wt_l, g_wt_l);
    cudaGetSymbolAddress((void**)&m1_h, g_m1_h); cudaGetSymbolAddress((void**)&m1_l, g_m1_l);
    cudaGetSymbolAddress((void**)&m2_h, g_m2_h); cudaGetSymbolAddress((void**)&m2_l, g_m2_l);
    cudaGetSymbolAddress((void**)&m3_h, g_m3_h); cudaGetSymbolAddress((void**)&m3_l, g_m3_l);
    cudaGetSymbolAddress((void**)&t1_h, g_t1_h); cudaGetSymbolAddress((void**)&t1_l, g_t1_l);
    cudaGetSymbolAddress((void**)&t2_h, g_t2_h); cudaGetSymbolAddress((void**)&t2_l, g_t2_l);

    const long long sEE = (long long)EB * EB;
    const long long sSE = (long long)SB * EB;
    const long long sQKV = (long long)SB * F3;
    dim3 gE(8, 8, NB);

    // 0) counters + input splits
    zero_k<<<(8 * HBINS + 255) / 256, 256>>>();
    split_k<<<dim3(4096, 1), 256>>>(x, xs_h, xs_l, 128, 0, 0);
    split_k<<<dim3(1536, 1), 256>>>(Wqkv, wq_h, wq_l, 128, 0, 0);

    // 1) qkv GEMM (fp32 out, +bias)
    gemm_mma<<<dim3(24, 64, 1), 256, GEMM_SMEM>>>(
        xs_h, xs_l, wq_h, wq_l, bqkv, qkv, EB, F3, 1.0f, 0, 0, 0);

    // 2) tile pruning, lazy-exact boundary resolution (thresholds bit-exact)
    norms_hist_k<<<8192, 256>>>();
    approx_median_k<<<8, 256>>>();
    candidates_k<<<8192, 256>>>();
    exact_dots_k<<<8 * CAP * 4 / 256, 256>>>(x, Wqkv, bqkv);
    exact_norm_k<<<8 * CAP / 256, 256>>>();
    cand_select_k<<<8, 1024>>>();
    mask_tiles2_k<<<8192, 256>>>();

    // 3) WO row pruning
    wo_rownorm_k<<<1024, 256>>>(WO);
    select_median_k<<<NB, 1024>>>(rnorm, SB, 1023, 1024, thr + 8);
    wmask_k<<<32, 256>>>();

    // 4) fused transposed splits (q, k, v, x, WOp) — one launch
    {
        SOp oq = { qkv,          nullptr, qt_h, qt_l, F3, sQKV, 0 };
        SOp ok = { qkv + EB,     nullptr, kt_h, kt_l, F3, sQKV, 0 };
        SOp ov = { qkv + 2 * EB, nullptr, vt_h, vt_l, F3, sQKV, 0 };
        SOp ox = { x,            nullptr, xt_h, xt_l, EB, sSE,  0 };
        SOp ow = { WO,           wmask,   wt_h, wt_l, EB, sSE,  SB };
        split_t5<<<dim3(32, 8, 5 * NB), 256>>>(oq, ok, ov, ox, ow);
    }

    // 5) chain with output swapping (gemm(A,B) = A.B^T), split epilogues:
    //    M1   = (1/32) Qp^T Kp      = gemm(qt, kt)
    //    M2^T = v^T x               = gemm(vt, xt)
    //    M3^T = x^T WOp             = gemm(xt, wt)
    //    T1   = M1.(M2^T)^T         = gemm(m1, m2t)
    //    T2^T = M3^T.T1^T           = gemm(m3t, t1)
    //    out  = x.(T2^T)^T          = gemm(xs, t2t)
    {
        GOp g0 = { qt_h, qt_l, kt_h, kt_l, m1_h, m1_l, 1.0f / 32.0f };
        GOp g1 = { vt_h, vt_l, xt_h, xt_l, m2_h, m2_l, 1.0f };
        GOp g2 = { xt_h, xt_l, wt_h, wt_l, m3_h, m3_l, 1.0f };
        gemm3_split<<<dim3(8, 8, 3 * NB), 256, GEMM_SMEM>>>(
            g0, g1, g2, SB, EB, sSE, sSE, sEE);
    }
    gemm_split<<<gE, 256, GEMM_SMEM>>>(m1_h, m1_l, m2_h, m2_l, t1_h, t1_l,
                                       EB, EB, 1.0f, sEE, sEE, sEE);
    gemm_split<<<gE, 256, GEMM_SMEM>>>(m3_h, m3_l, t1_h, t1_l, t2_h, t2_l,
                                       EB, EB, 1.0f, sEE, sEE, sEE);
    gemm_mma<<<dim3(8, 16, NB), 256, GEMM_SMEM>>>(xs_h, xs_l, t2_h, t2_l, nullptr, out,
                                                  EB, EB, 1.0f, sSE, sEE, sSE);
}

// round 13
// speedup vs baseline: 2.2182x; 1.0063x over previous
#include <cuda_runtime.h>
#include <cuda_bf16.h>
#include <math.h>
#include <stdint.h>

// Problem constants
#define SB 2048
#define EB 1024
#define NB 4
#define F3 3072
#define NTILES 524288
#define CAP 16384
#define HBINS 8192
#define DELTA 2.5e-3f

// ---------------- scratch (device globals) ---------------------------------
__device__ float g_qkv[NB * SB * F3];
__device__ float g_normq[NB * NTILES];
__device__ float g_normk[NB * NTILES];
__device__ float g_rnorm[NB * SB];
__device__ float g_thr[12];
__device__ float g_thra[8];
__device__ float g_wmask[NB * SB];
__device__ unsigned g_hist[8 * HBINS];
__device__ unsigned g_ccnt[8];
__device__ unsigned g_below[8];
__device__ int   g_cidx[8 * CAP];
__device__ float g_cval[8 * CAP * 4];
__device__ float g_cnorm[8 * CAP];

// bf16 split operands (plain row-major, ld = K)
__device__ __align__(16) __nv_bfloat16 g_xs_h[8388608], g_xs_l[8388608];   // x [8192,1024]
__device__ __align__(16) __nv_bfloat16 g_wq_h[3145728], g_wq_l[3145728];   // Wqkv
__device__ __align__(16) __nv_bfloat16 g_qt_h[8388608], g_qt_l[8388608];   // Qp^T
__device__ __align__(16) __nv_bfloat16 g_kt_h[8388608], g_kt_l[8388608];   // Kp^T
__device__ __align__(16) __nv_bfloat16 g_vt_h[8388608], g_vt_l[8388608];   // v^T
__device__ __align__(16) __nv_bfloat16 g_xt_h[8388608], g_xt_l[8388608];   // x^T
__device__ __align__(16) __nv_bfloat16 g_wt_h[8388608], g_wt_l[8388608];   // WOp^T
__device__ __align__(16) __nv_bfloat16 g_m1_h[4194304], g_m1_l[4194304];   // M1
__device__ __align__(16) __nv_bfloat16 g_m2_h[4194304], g_m2_l[4194304];   // M2^T
__device__ __align__(16) __nv_bfloat16 g_m3_h[4194304], g_m3_l[4194304];   // M3^T
__device__ __align__(16) __nv_bfloat16 g_t1_h[4194304], g_t1_l[4194304];   // T1
__device__ __align__(16) __nv_bfloat16 g_t2_h[4194304], g_t2_l[4194304];   // T2^T

// ======================= PTX helpers =======================================
__device__ __forceinline__ uint32_t smem_u32(const void* p) {
    uint32_t a;
    asm("{ .reg .u64 t; cvta.to.shared.u64 t, %1; cvt.u32.u64 %0, t; }"
        : "=r"(a) : "l"(p));
    return a;
}
#define CP16(dst, src) \
    asm volatile("cp.async.cg.shared.global [%0], [%1], 16;" :: "r"(dst), "l"(src))
#define CP_COMMIT() asm volatile("cp.async.commit_group;" ::: "memory")
#define CP_WAIT2()  asm volatile("cp.async.wait_group 2;" ::: "memory")

__device__ __forceinline__ void ldsm4(uint32_t* r, uint32_t addr) {
    asm volatile("ldmatrix.sync.aligned.m8n8.x4.shared.b16 {%0,%1,%2,%3}, [%4];"
        : "=r"(r[0]), "=r"(r[1]), "=r"(r[2]), "=r"(r[3]) : "r"(addr));
}
__device__ __forceinline__ void mma16816(float* d, const uint32_t* a,
                                         uint32_t b0, uint32_t b1) {
    asm volatile(
        "mma.sync.aligned.m16n8k16.row.col.f32.bf16.bf16.f32 "
        "{%0,%1,%2,%3}, {%4,%5,%6,%7}, {%8,%9}, {%0,%1,%2,%3};"
        : "+f"(d[0]), "+f"(d[1]), "+f"(d[2]), "+f"(d[3])
        : "r"(a[0]), "r"(a[1]), "r"(a[2]), "r"(a[3]), "r"(b0), "r"(b1));
}

// ======================= split helpers =====================================
union Pack8 { unsigned short u[8]; uint4 v; };

__device__ __forceinline__ void split8(const float* f, uint4& hv, uint4& lv) {
    Pack8 h, l;
    #pragma unroll
    for (int j = 0; j < 8; j++) {
        float v = f[j];
        __nv_bfloat16 bh = __float2bfloat16(v);
        float rem = v - __bfloat162float(bh);
        __nv_bfloat16 bl = __float2bfloat16(rem);
        h.u[j] = *(unsigned short*)&bh;
        l.u[j] = *(unsigned short*)&bl;
    }
    hv = h.v; lv = l.v;
}

__device__ __forceinline__ void split2(float v0, float v1,
                                       uint32_t& hw, uint32_t& lw) {
    __nv_bfloat16 h0 = __float2bfloat16(v0);
    __nv_bfloat16 h1 = __float2bfloat16(v1);
    float r0 = v0 - __bfloat162float(h0);
    float r1 = v1 - __bfloat162float(h1);
    __nv_bfloat16 l0 = __float2bfloat16(r0);
    __nv_bfloat16 l1 = __float2bfloat16(r1);
    hw = (uint32_t)(*(unsigned short*)&h0) | ((uint32_t)(*(unsigned short*)&h1) << 16);
    lw = (uint32_t)(*(unsigned short*)&l0) | ((uint32_t)(*(unsigned short*)&l1) << 16);
}

// K-major (row-major) source -> row-major bf16 hi/lo
__global__ __launch_bounds__(256) void split_k(
    const float* __restrict__ src, __nv_bfloat16* __restrict__ dh,
    __nv_bfloat16* __restrict__ dl, int K8,
    long long srcStride, long long dstStride)
{
    int idx = blockIdx.x * 256 + threadIdx.x;
    int z = blockIdx.y;
    int r = idx / K8, g = idx - r * K8;
    const float* sp = src + z * srcStride + (size_t)r * (K8 * 8) + g * 8;
    float f[8];
    *(float4*)(f)     = *(const float4*)(sp);
    *(float4*)(f + 4) = *(const float4*)(sp + 4);
    uint4 hv, lv; split8(f, hv, lv);
    size_t off = z * dstStride + (size_t)r * (K8 * 8) + g * 8;
    *(uint4*)(dh + off) = hv;
    *(uint4*)(dl + off) = lv;
}

// Fused transposed splits with optional inline tile-mask: 5 ops x NB batches.
// out[r][k] = src[k*ldkSrc + r] * (scale?[k]); zeroed when the 2x2 tile norm
// (tile index (k>>1, r>>1) in (s,d) space) is below thr[z].
struct SOp {
    const float* src;
    const float* scale;         // per-k scale (WO mask) or null
    const float* norm;          // tile norms (g_normq/g_normk) or null
    const float* thr;           // per-batch thresholds (g_thr+0 / +4) or null
    __nv_bfloat16* dh;
    __nv_bfloat16* dl;
    int ldkSrc;
    long long srcStride;
    int scaleStride;
};

__global__ __launch_bounds__(256) void split_t5(SOp o0, SOp o1, SOp o2, SOp o3, SOp o4)
{
    __shared__ float t[64][132];
    int zb = blockIdx.z;
    int opi = zb >> 2, z = zb & 3;
    SOp op = (opi == 0) ? o0 : (opi == 1) ? o1 : (opi == 2) ? o2 : (opi == 3) ? o3 : o4;
    int k0 = blockIdx.x * 64, r0 = blockIdx.y * 128;
    int tid = threadIdx.x;
    int rr = tid & 127, kk = tid >> 7;
    const float* sp = op.src + z * op.srcStride;
    const float* sc = op.scale ? op.scale + (size_t)z * op.scaleStride : nullptr;
    for (int k = kk; k < 64; k += 2) {
        float v = sp[(size_t)(k0 + k) * op.ldkSrc + r0 + rr];
        if (sc) v *= sc[k0 + k];
        t[k][rr] = v;
    }
    __syncthreads();
    const long long dstStride = (long long)SB * EB;
    const float* nb = op.norm ? op.norm + (size_t)z * NTILES : nullptr;
    float th = op.thr ? op.thr[z] : 0.0f;
    #pragma unroll
    for (int q = 0; q < 4; q++) {
        int task = tid + 256 * q;
        int r = task >> 3, c8 = task & 7;
        float f[8];
        #pragma unroll
        for (int j = 0; j < 8; j++) f[j] = t[c8 * 8 + j][r];
        if (nb) {
            int drow = (r0 + r) >> 1;               // d/2
            #pragma unroll
            for (int j = 0; j < 8; j += 2) {
                int srow = (k0 + c8 * 8 + j) >> 1;  // s/2
                if (nb[srow * 512 + drow] < th) { f[j] = 0.0f; f[j + 1] = 0.0f; }
            }
        }
        uint4 hv, lv; split8(f, hv, lv);
        size_t off = z * dstStride + (size_t)(r0 + r) * SB + k0 + c8 * 8;
        *(uint4*)(op.dh + off) = hv;
        *(uint4*)(op.dl + off) = lv;
    }
}

// ======================= bf16-split HMMA GEMM (proven R11 core) ============
// C = A_f32 . B_f32^T, 3-segment K concat: A=[hi|lo|hi], B=[hi|hi|lo].
// CTA tile 128x128, 256 threads (4x2 warp grid, 32x64 warp tiles), BK=32,
// 4-stage cp.async ring, prefetch distance 3, 1 syncthreads per chunk.
#define AROWB 80
#define ATILEB (128 * AROWB)
#define STGB (2 * ATILEB)
#define NSTAGE 4
#define GEMM_SMEM (NSTAGE * STGB)      // 81920

__device__ __forceinline__ void gemm_core(
    uint32_t sb, int tid,
    const __nv_bfloat16* __restrict__ Ahi, const __nv_bfloat16* __restrict__ Alo,
    const __nv_bfloat16* __restrict__ Bhi, const __nv_bfloat16* __restrict__ Blo,
    int K, int m0, int n0, float (&d)[2][8][4])
{
    const int lane = tid & 31, w = tid >> 5;
    const int wm = w & 3, wn = w >> 2;
    const __nv_bfloat16* Aseg[3] = { Ahi, Alo, Ahi };
    const __nv_bfloat16* Bseg[3] = { Bhi, Bhi, Blo };
    const int cps = K >> 5;
    const int C3 = 3 * cps;

    auto issue = [&](int c) {
        int st = c & (NSTAGE - 1);
        int seg = c / cps, bk = (c - seg * cps) << 5;
        uint32_t ab = sb + st * STGB, bb = ab + ATILEB;
        const __nv_bfloat16* As = Aseg[seg];
        const __nv_bfloat16* Bs = Bseg[seg];
        #pragma unroll
        for (int h = 0; h < 2; h++) {
            int id = tid + h * 256;
            int r = id >> 2, cc = id & 3;
            CP16(ab + r * AROWB + cc * 16, As + (size_t)(m0 + r) * K + bk + cc * 8);
            CP16(bb + r * AROWB + cc * 16, Bs + (size_t)(n0 + r) * K + bk + cc * 8);
        }
        CP_COMMIT();
    };
    issue(0); issue(1); issue(2);

    #pragma unroll
    for (int i = 0; i < 2; i++)
        #pragma unroll
        for (int j = 0; j < 8; j++)
            #pragma unroll
            for (int q = 0; q < 4; q++) d[i][j][q] = 0.0f;

    for (int c = 0; c < C3; c++) {
        CP_WAIT2();
        __syncthreads();
        if (c + 3 < C3) issue(c + 3); else CP_COMMIT();
        int st = c & (NSTAGE - 1);
        uint32_t ab = sb + st * STGB, bb = ab + ATILEB;
        #pragma unroll
        for (int ks = 0; ks < 2; ks++) {
            uint32_t colB = ks * 32 + ((lane >> 4) << 4);
            uint32_t ar[2][4], br[4][4];
            #pragma unroll
            for (int mt = 0; mt < 2; mt++)
                ldsm4(ar[mt], ab + (wm * 32 + mt * 16 + (lane & 15)) * AROWB + colB);
            #pragma unroll
            for (int ng = 0; ng < 4; ng++)
                ldsm4(br[ng], bb + (wn * 64 + ng * 16 + (lane & 15)) * AROWB + colB);
            #pragma unroll
            for (int mt = 0; mt < 2; mt++)
                #pragma unroll
                for (int ng = 0; ng < 4; ng++) {
                    mma16816(d[mt][2 * ng],     ar[mt], br[ng][0], br[ng][2]);
                    mma16816(d[mt][2 * ng + 1], ar[mt], br[ng][1], br[ng][3]);
                }
        }
    }
}

// fp32 epilogue GEMM (qkv with bias; final out)
__global__ __launch_bounds__(256, 2) void gemm_mma(
    const __nv_bfloat16* __restrict__ Ahi, const __nv_bfloat16* __restrict__ Alo,
    const __nv_bfloat16* __restrict__ Bhi, const __nv_bfloat16* __restrict__ Blo,
    const float* __restrict__ bias, float* __restrict__ C,
    int K, int ldc, float alpha,
    long long aStr, long long bStr, long long cStr)
{
    extern __shared__ char smem[];
    uint32_t sb = smem_u32(smem);
    const int tid = threadIdx.x, lane = tid & 31, w = tid >> 5;
    const int wm = w & 3, wn = w >> 2;
    const int m0 = blockIdx.y * 128, n0 = blockIdx.x * 128, z = blockIdx.z;
    float d[2][8][4];
    gemm_core(sb, tid, Ahi + z * aStr, Alo + z * aStr,
              Bhi + z * bStr, Blo + z * bStr, K, m0, n0, d);

    const int gr = lane >> 2, qc = lane & 3;
    float* Cb = C + (size_t)z * cStr;
    #pragma unroll
    for (int mt = 0; mt < 2; mt++) {
        #pragma unroll
        for (int nt = 0; nt < 8; nt++) {
            int mrow = m0 + wm * 32 + mt * 16 + gr;
            int ncol = n0 + wn * 64 + nt * 8 + qc * 2;
            float b0 = 0.0f, b1 = 0.0f;
            if (bias) { float2 bv = *(const float2*)(bias + ncol); b0 = bv.x; b1 = bv.y; }
            float2 v0 = make_float2(d[mt][nt][0] * alpha + b0, d[mt][nt][1] * alpha + b1);
            float2 v1 = make_float2(d[mt][nt][2] * alpha + b0, d[mt][nt][3] * alpha + b1);
            *(float2*)(Cb + (size_t)mrow * ldc + ncol) = v0;
            *(float2*)(Cb + (size_t)(mrow + 8) * ldc + ncol) = v1;
        }
    }
}

// split epilogue: write hi/lo bf16 directly (no fp32 intermediate)
__device__ __forceinline__ void epilogue_split(
    int tid, int m0, int n0, float (&d)[2][8][4], float alpha,
    __nv_bfloat16* __restrict__ Ch, __nv_bfloat16* __restrict__ Cl, int ldc)
{
    const int lane = tid & 31, w = tid >> 5;
    const int wm = w & 3, wn = w >> 2;
    const int gr = lane >> 2, qc = lane & 3;
    #pragma unroll
    for (int mt = 0; mt < 2; mt++) {
        #pragma unroll
        for (int nt = 0; nt < 8; nt++) {
            int mrow = m0 + wm * 32 + mt * 16 + gr;
            int ncol = n0 + wn * 64 + nt * 8 + qc * 2;
            uint32_t hw, lw;
            split2(d[mt][nt][0] * alpha, d[mt][nt][1] * alpha, hw, lw);
            *(uint32_t*)(Ch + (size_t)mrow * ldc + ncol) = hw;
            *(uint32_t*)(Cl + (size_t)mrow * ldc + ncol) = lw;
            split2(d[mt][nt][2] * alpha, d[mt][nt][3] * alpha, hw, lw);
            *(uint32_t*)(Ch + (size_t)(mrow + 8) * ldc + ncol) = hw;
            *(uint32_t*)(Cl + (size_t)(mrow + 8) * ldc + ncol) = lw;
        }
    }
}

// single-op GEMM with split epilogue (T1, T2^T)
__global__ __launch_bounds__(256, 2) void gemm_split(
    const __nv_bfloat16* __restrict__ Ahi, const __nv_bfloat16* __restrict__ Alo,
    const __nv_bfloat16* __restrict__ Bhi, const __nv_bfloat16* __restrict__ Blo,
    __nv_bfloat16* __restrict__ Ch, __nv_bfloat16* __restrict__ Cl,
    int K, int ldc, float alpha,
    long long aStr, long long bStr, long long cStr)
{
    extern __shared__ char smem[];
    uint32_t sb = smem_u32(smem);
    const int tid = threadIdx.x;
    const int m0 = blockIdx.y * 128, n0 = blockIdx.x * 128, z = blockIdx.z;
    float d[2][8][4];
    gemm_core(sb, tid, Ahi + z * aStr, Alo + z * aStr,
              Bhi + z * bStr, Blo + z * bStr, K, m0, n0, d);
    epilogue_split(tid, m0, n0, d, alpha,
                   Ch + (size_t)z * cStr, Cl + (size_t)z * cStr, ldc);
}

// fused 3-op GEMM (M1, M2^T, M3^T), z = op*NB + b, split epilogue
struct GOp {
    const __nv_bfloat16 *Ah, *Al, *Bh, *Bl;
    __nv_bfloat16 *Ch, *Cl;
    float alpha;
};

__global__ __launch_bounds__(256, 2) void gemm3_split(
    GOp o0, GOp o1, GOp o2, int K, int ldc,
    long long aStr, long long bStr, long long cStr)
{
    extern __shared__ char smem[];
    uint32_t sb = smem_u32(smem);
    const int tid = threadIdx.x;
    int zb = blockIdx.z;
    int opi = zb >> 2, z = zb & 3;
    GOp op = (opi == 0) ? o0 : (opi == 1) ? o1 : o2;
    const int m0 = blockIdx.y * 128, n0 = blockIdx.x * 128;
    float d[2][8][4];
    gemm_core(sb, tid, op.Ah + z * aStr, op.Al + z * aStr,
              op.Bh + z * bStr, op.Bl + z * bStr, K, m0, n0, d);
    epilogue_split(tid, m0, n0, d, op.alpha,
                   op.Ch + (size_t)z * cStr, op.Cl + (size_t)z * cStr, ldc);
}

// ======================= pruning pipeline (proven) =========================
__global__ void zero_k()
{
    int i = blockIdx.x * 256 + threadIdx.x;
    if (i < 8 * HBINS) g_hist[i] = 0;
    if (i < 8) { g_ccnt[i] = 0; g_below[i] = 0; }
}

__global__ void norms_hist_k()
{
    int idx = blockIdx.x * 256 + threadIdx.x;
    int b = idx >> 19;
    int r = idx & (NTILES - 1);
    int s2 = r >> 9, d2 = r & 511;
    size_t base = ((size_t)(b * SB + 2 * s2)) * F3 + 2 * d2;
    #pragma unroll
    for (int qk = 0; qk < 2; qk++) {
        size_t p = base + qk * EB;
        float2 a = *(const float2*)&g_qkv[p];
        float2 c = *(const float2*)&g_qkv[p + F3];
        float s00 = __fmul_rn(a.x, a.x);
        float s01 = __fmul_rn(a.y, a.y);
        float s10 = __fmul_rn(c.x, c.x);
        float s11 = __fmul_rn(c.y, c.y);
        float nm = sqrtf(__fadd_rn(__fadd_rn(__fadd_rn(s00, s01), s10), s11));
        if (qk == 0) g_normq[idx] = nm; else g_normk[idx] = nm;
        int bin = (int)(nm * 1024.0f);
        if (bin < 0) bin = 0;
        if (bin > HBINS - 1) bin = HBINS - 1;
        atomicAdd(&g_hist[(qk * 4 + b) * HBINS + bin], 1u);
    }
}

__global__ __launch_bounds__(256) void approx_median_k()
{
    __shared__ unsigned part[256];
    int g = blockIdx.x, tid = threadIdx.x;
    const unsigned* h = &g_hist[g * HBINS];
    unsigned s = 0;
    for (int i = tid * 32; i < tid * 32 + 32; i++) s += h[i];
    part[tid] = s;
    __syncthreads();
    if (tid == 0) {
        unsigned k = 262143, cum = 0;
        int seg = 0;
        while (seg < 256 && cum + part[seg] <= k) { cum += part[seg]; seg++; }
        int bin = seg * 32;
        while (true) { unsigned c = h[bin]; if (cum + c > k) break; cum += c; bin++; }
        g_thra[g] = ((float)bin + 0.5f) * (1.0f / 1024.0f);
    }
}

__global__ void candidates_k()
{
    int idx = blockIdx.x * 256 + threadIdx.x;
    int b = idx >> 19;
    int r = idx & (NTILES - 1);
    #pragma unroll
    for (int qk = 0; qk < 2; qk++) {
        float nm = qk ? g_normk[idx] : g_normq[idx];
        int g = qk * 4 + b;
        float d = nm - g_thra[g];
        if (fabsf(d) <= DELTA) {
            unsigned pos = atomicAdd(&g_ccnt[g], 1u);
            if (pos < CAP) g_cidx[g * CAP + pos] = r;
        } else if (d < 0.0f) {
            atomicAdd(&g_below[g], 1u);
        }
    }
}

__device__ __forceinline__ float comp_dot(
    const float* __restrict__ a, const float* __restrict__ b, float bias)
{
    float s = 0.0f, c = 0.0f;
    for (int k = 0; k < EB; k++) {
        float av = a[k], bv = b[k];
        float p = __fmul_rn(av, bv);
        float e = __fmaf_rn(av, bv, -p);
        float t = __fadd_rn(s, p);
        float z = (fabsf(s) >= fabsf(p))
                  ? __fadd_rn(__fadd_rn(s, -t), p)
                  : __fadd_rn(__fadd_rn(p, -t), s);
        c = __fadd_rn(c, __fadd_rn(z, e));
        s = t;
    }
    float v = __fadd_rn(s, c);
    return __fadd_rn(v, bias);
}

__global__ void exact_dots_k(const float* __restrict__ x,
                             const float* __restrict__ Wqkv,
                             const float* __restrict__ bqkv)
{
    int flat = blockIdx.x * 256 + threadIdx.x;
    int e    = flat & 3;
    int cand = (flat >> 2) & (CAP - 1);
    int g    = flat >> 16;
    if (g >= 8) return;
    unsigned cnt = g_ccnt[g]; if (cnt > CAP) cnt = CAP;
    if ((unsigned)cand >= cnt) return;
    int r  = g_cidx[g * CAP + cand];
    int qk = g >> 2, b = g & 3;
    int s2 = r >> 9, d2 = r & 511;
    int srow = 2 * s2 + (e >> 1);
    int dcol = 2 * d2 + (e & 1) + qk * EB;
    float v = comp_dot(x + ((size_t)(b * SB + srow)) * EB,
                       Wqkv + (size_t)dcol * EB, bqkv[dcol]);
    g_cval[(size_t)(g * CAP + cand) * 4 + e] = v;
}

__global__ void exact_norm_k()
{
    int flat = blockIdx.x * 256 + threadIdx.x;
    int cand = flat & (CAP - 1);
    int g    = flat >> 14;
    if (g >= 8) return;
    unsigned cnt = g_ccnt[g]; if (cnt > CAP) cnt = CAP;
    if ((unsigned)cand >= cnt) return;
    const float* v = &g_cval[(size_t)(g * CAP + cand) * 4];
    float s00 = __fmul_rn(v[0], v[0]);
    float s01 = __fmul_rn(v[1], v[1]);
    float s10 = __fmul_rn(v[2], v[2]);
    float s11 = __fmul_rn(v[3], v[3]);
    float nm = sqrtf(__fadd_rn(__fadd_rn(__fadd_rn(s00, s01), s10), s11));
    g_cnorm[g * CAP + cand] = nm;
    int r = g_cidx[g * CAP + cand];
    int b = g & 3;
    if ((g >> 2) == 0) g_normq[b * NTILES + r] = nm;
    else               g_normk[b * NTILES + r] = nm;
}

__global__ __launch_bounds__(1024) void cand_select_k()
{
    __shared__ float s_v1, s_v2;
    int g = blockIdx.x;
    unsigned cnt = g_ccnt[g]; if (cnt > CAP) cnt = CAP;
    long long below = (long long)g_below[g];
    long long r1 = 262143LL - below;
    long long r2 = 262144LL - below;
    const float* cn = &g_cnorm[g * CAP];
    for (unsigned i = threadIdx.x; i < cnt; i += 1024) {
        float v = cn[i];
        long long less = 0, eq = 0;
        for (unsigned j = 0; j < cnt; j++) {
            float w = cn[j];
            less += (w < v);
            eq   += (w == v);
        }
        if (less <= r1 && r1 < less + eq) s_v1 = v;
        if (less <= r2 && r2 < less + eq) s_v2 = v;
    }
    __syncthreads();
    if (threadIdx.x == 0)
        g_thr[g] = __fmul_rn(0.5f, __fadd_rn(s_v1, s_v2));
}

__global__ void wo_rownorm_k(const float* __restrict__ WO)
{
    int warp = threadIdx.x >> 5, lane = threadIdx.x & 31;
    int row = blockIdx.x * 8 + warp;
    const float* p = WO + (size_t)row * EB;
    float s = 0.0f, c = 0.0f;
    for (int d = lane; d < EB; d += 32) {
        float v = p[d];
        float pr = __fmul_rn(v, v);
        float e  = __fmaf_rn(v, v, -pr);
        float t  = __fadd_rn(s, pr);
        float z  = (fabsf(s) >= fabsf(pr))
                   ? __fadd_rn(__fadd_rn(s, -t), pr)
                   : __fadd_rn(__fadd_rn(pr, -t), s);
        c = __fadd_rn(c, __fadd_rn(z, e));
        s = t;
    }
    float tot_s = s, tot_c = c;
    #pragma unroll
    for (int o = 16; o; o >>= 1) {
        float os = __shfl_xor_sync(0xffffffffu, tot_s, o);
        float oc = __shfl_xor_sync(0xffffffffu, tot_c, o);
        float t = __fadd_rn(tot_s, os);
        float z = (fabsf(tot_s) >= fabsf(os))
                  ? __fadd_rn(__fadd_rn(tot_s, -t), os)
                  : __fadd_rn(__fadd_rn(os, -t), tot_s);
        tot_c = __fadd_rn(__fadd_rn(tot_c, oc), z);
        tot_s = t;
    }
    if (lane == 0) g_rnorm[row] = sqrtf(__fadd_rn(tot_s, tot_c));
}

__global__ __launch_bounds__(1024) void select_median_k(
    const float* __restrict__ data, int N, int k1, int k2, float* __restrict__ out)
{
    __shared__ unsigned hist[256];
    __shared__ unsigned s_prefix, s_pmask;
    __shared__ int s_k;
    __shared__ float s_v[2];
    const float* d = data + (size_t)blockIdx.x * N;
    const int tid = threadIdx.x;
    for (int which = 0; which < 2; which++) {
        int k = which ? k2 : k1;
        unsigned prefix = 0, pmask = 0;
        for (int pass = 0; pass < 4; pass++) {
            int shift = 24 - 8 * pass;
            if (tid < 256) hist[tid] = 0;
            __syncthreads();
            for (int i = tid; i < N; i += 1024) {
                unsigned u = __float_as_uint(d[i]);
                if ((u & pmask) == prefix) atomicAdd(&hist[(u >> shift) & 255], 1u);
            }
            __syncthreads();
            if (tid == 0) {
                int cum = 0, bin = 0;
                for (; bin < 256; bin++) {
                    int cc = (int)hist[bin];
                    if (cum + cc > k) break;
                    cum += cc;
                }
                s_prefix = prefix | ((unsigned)bin << shift);
                s_pmask  = pmask  | (255u << shift);
                s_k = k - cum;
            }
            __syncthreads();
            prefix = s_prefix; pmask = s_pmask; k = s_k;
        }
        if (tid == 0) s_v[which] = __uint_as_float(prefix);
        __syncthreads();
    }
    if (tid == 0) out[blockIdx.x] = __fmul_rn(0.5f, __fadd_rn(s_v[0], s_v[1]));
}

__global__ void wmask_k()
{
    int idx = blockIdx.x * 256 + threadIdx.x;
    int b = idx >> 11;
    g_wmask[idx] = (g_rnorm[idx] >= g_thr[8 + b]) ? 1.0f : 0.0f;
}

// ======================= launch (single stream, capture-safe) ==============
extern "C" void kernel_launch(void* const* d_in, const int* in_sizes, int n_in,
                              void* d_out, int out_size)
{
    const float* x    = (const float*)d_in[0];
    const float* Wqkv = (const float*)d_in[1];
    const float* bqkv = (const float*)d_in[2];
    const float* WO   = (const float*)d_in[3];
    float* out = (float*)d_out;

    cudaFuncSetAttribute(gemm_mma,    cudaFuncAttributeMaxDynamicSharedMemorySize, GEMM_SMEM);
    cudaFuncSetAttribute(gemm_split,  cudaFuncAttributeMaxDynamicSharedMemorySize, GEMM_SMEM);
    cudaFuncSetAttribute(gemm3_split, cudaFuncAttributeMaxDynamicSharedMemorySize, GEMM_SMEM);

    float *qkv, *rnorm, *thr, *wmask, *normq, *normk;
    cudaGetSymbolAddress((void**)&qkv,   g_qkv);
    cudaGetSymbolAddress((void**)&rnorm, g_rnorm);
    cudaGetSymbolAddress((void**)&thr,   g_thr);
    cudaGetSymbolAddress((void**)&wmask, g_wmask);
    cudaGetSymbolAddress((void**)&normq, g_normq);
    cudaGetSymbolAddress((void**)&normk, g_normk);

    __nv_bfloat16 *xs_h, *xs_l, *wq_h, *wq_l, *qt_h, *qt_l, *kt_h, *kt_l;
    __nv_bfloat16 *vt_h, *vt_l, *xt_h, *xt_l, *wt_h, *wt_l;
    __nv_bfloat16 *m1_h, *m1_l, *m2_h, *m2_l, *m3_h, *m3_l;
    __nv_bfloat16 *t1_h, *t1_l, *t2_h, *t2_l;
    cudaGetSymbolAddress((void**)&xs_h, g_xs_h); cudaGetSymbolAddress((void**)&xs_l, g_xs_l);
    cudaGetSymbolAddress((void**)&wq_h, g_wq_h); cudaGetSymbolAddress((void**)&wq_l, g_wq_l);
    cudaGetSymbolAddress((void**)&qt_h, g_qt_h); cudaGetSymbolAddress((void**)&qt_l, g_qt_l);
    cudaGetSymbolAddress((void**)&kt_h, g_kt_h); cudaGetSymbolAddress((void**)&kt_l, g_kt_l);
    cudaGetSymbolAddress((void**)&vt_h, g_vt_h); cudaGetSymbolAddress((void**)&vt_l, g_vt_l);
    cudaGetSymbolAddress((void**)&xt_h, g_xt_h); cudaGetSymbolAddress((void**)&xt_l, g_xt_l);
    cudaGetSymbolAddress((void**)&wt_h, g_wt_h); cudaGetSymbolAddress((void**)&wt_l, g_wt_l);
    cudaGetSymbolAddress((void**)&m1_h, g_m1_h); cudaGetSymbolAddress((void**)&m1_l, g_m1_l);
    cudaGetSymbolAddress((void**)&m2_h, g_m2_h); cudaGetSymbolAddress((void**)&m2_l, g_m2_l);
    cudaGetSymbolAddress((void**)&m3_h, g_m3_h); cudaGetSymbolAddress((void**)&m3_l, g_m3_l);
    cudaGetSymbolAddress((void**)&t1_h, g_t1_h); cudaGetSymbolAddress((void**)&t1_l, g_t1_l);
    cudaGetSymbolAddress((void**)&t2_h, g_t2_h); cudaGetSymbolAddress((void**)&t2_l, g_t2_l);

    const long long sEE = (long long)EB * EB;
    const long long sSE = (long long)SB * EB;
    const long long sQKV = (long long)SB * F3;
    dim3 gE(8, 8, NB);

    // 0) counters + input splits
    zero_k<<<(8 * HBINS + 255) / 256, 256>>>();
    split_k<<<dim3(4096, 1), 256>>>(x, xs_h, xs_l, 128, 0, 0);
    split_k<<<dim3(1536, 1), 256>>>(Wqkv, wq_h, wq_l, 128, 0, 0);

    // 1) qkv GEMM (fp32 out, +bias)
    gemm_mma<<<dim3(24, 64, 1), 256, GEMM_SMEM>>>(
        xs_h, xs_l, wq_h, wq_l, bqkv, qkv, EB, F3, 1.0f, 0, 0, 0);

    // 2) tile pruning, lazy-exact boundary resolution (thresholds bit-exact)
    norms_hist_k<<<8192, 256>>>();
    approx_median_k<<<8, 256>>>();
    candidates_k<<<8192, 256>>>();
    exact_dots_k<<<8 * CAP * 4 / 256, 256>>>(x, Wqkv, bqkv);
    exact_norm_k<<<8 * CAP / 256, 256>>>();
    cand_select_k<<<8, 1024>>>();

    // 3) WO row pruning
    wo_rownorm_k<<<1024, 256>>>(WO);
    select_median_k<<<NB, 1024>>>(rnorm, SB, 1023, 1024, thr + 8);
    wmask_k<<<32, 256>>>();

    // 4) fused transposed splits; q/k masked inline via exact norms+thresholds
    {
        SOp oq = { qkv,          nullptr, normq,   thr,     qt_h, qt_l, F3, sQKV, 0 };
        SOp ok = { qkv + EB,     nullptr, normk,   thr + 4, kt_h, kt_l, F3, sQKV, 0 };
        SOp ov = { qkv + 2 * EB, nullptr, nullptr, nullptr, vt_h, vt_l, F3, sQKV, 0 };
        SOp ox = { x,            nullptr, nullptr, nullptr, xt_h, xt_l, EB, sSE,  0 };
        SOp ow = { WO,           wmask,   nullptr, nullptr, wt_h, wt_l, EB, sSE,  SB };
        split_t5<<<dim3(32, 8, 5 * NB), 256>>>(oq, ok, ov, ox, ow);
    }

    // 5) chain with output swapping (gemm(A,B) = A.B^T), split epilogues:
    //    M1   = (1/32) Qp^T Kp      = gemm(qt, kt)
    //    M2^T = v^T x               = gemm(vt, xt)
    //    M3^T = x^T WOp             = gemm(xt, wt)
    //    T1   = M1.(M2^T)^T         = gemm(m1, m2t)
    //    T2^T = M3^T.T1^T           = gemm(m3t, t1)
    //    out  = x.(T2^T)^T          = gemm(xs, t2t)
    {
        GOp g0 = { qt_h, qt_l, kt_h, kt_l, m1_h, m1_l, 1.0f / 32.0f };
        GOp g1 = { vt_h, vt_l, xt_h, xt_l, m2_h, m2_l, 1.0f };
        GOp g2 = { xt_h, xt_l, wt_h, wt_l, m3_h, m3_l, 1.0f };
        gemm3_split<<<dim3(8, 8, 3 * NB), 256, GEMM_SMEM>>>(
            g0, g1, g2, SB, EB, sSE, sSE, sEE);
    }
    gemm_split<<<gE, 256, GEMM_SMEM>>>(m1_h, m1_l, m2_h, m2_l, t1_h, t1_l,
                                       EB, EB, 1.0f, sEE, sEE, sEE);
    gemm_split<<<gE, 256, GEMM_SMEM>>>(m3_h, m3_l, t1_h, t1_l, t2_h, t2_l,
                                       EB, EB, 1.0f, sEE, sEE, sEE);
    gemm_mma<<<dim3(8, 16, NB), 256, GEMM_SMEM>>>(xs_h, xs_l, t2_h, t2_l, nullptr, out,
                                                  EB, EB, 1.0f, sSE, sEE, sSE);
}